// round 1
// baseline (speedup 1.0000x reference)
#include <cuda_runtime.h>
#include <cuda_bf16.h>
#include <math.h>

// ---------------- problem constants ----------------
#define L 512
#define NSEQ 256
#define DM 64          // D_MSA
#define DS 32          // D_STATE
#define NH 4           // heads
#define DK 32
#define DV 16
#define FFH 256        // D_MSA * R_FF
#define NROWS (NSEQ * L)   // 131072
#define EPSLN 1e-5f
#define NEGMAX (-3.402823466e38f)

// ---------------- scratch (device globals: no runtime allocs) ----------------
__device__ float g_q[L * NH * DK];            // (l, h*32+d)
__device__ float g_k[L * NH * DK];
__device__ float g_attn[NH * L * L];          // (h, i, j)
__device__ float g_vT[NH * L * NSEQ * DV];    // (h, j, n*16+d)
__device__ float g_attout[NROWS * DM];        // (n*512+i, h*16+d)
__device__ float g_msax[NROWS * DM];          // msa + attn_out (post-residual)

// =====================================================================
// K1: st = LN(state); q = st@Wq+bq; k = st@Wk+bk.  grid=512, block=128
// =====================================================================
__global__ void qk_kernel(const float* __restrict__ state,
                          const float* __restrict__ nsg, const float* __restrict__ nsb,
                          const float* __restrict__ Wq, const float* __restrict__ bq,
                          const float* __restrict__ Wk, const float* __restrict__ bk) {
    int l = blockIdx.x;
    int t = threadIdx.x;                // 0..127
    __shared__ float st[DS];
    if (t < DS) {
        float x = state[l * DS + t];
        float s = x;
        #pragma unroll
        for (int o = 16; o; o >>= 1) s += __shfl_xor_sync(0xffffffffu, s, o);
        float m = s * (1.0f / DS);
        float d = x - m;
        float v = d * d;
        #pragma unroll
        for (int o = 16; o; o >>= 1) v += __shfl_xor_sync(0xffffffffu, v, o);
        float r = rsqrtf(v * (1.0f / DS) + EPSLN);
        st[t] = d * r * nsg[t] + nsb[t];
    }
    __syncthreads();
    float aq = bq[t], ak = bk[t];
    #pragma unroll
    for (int c = 0; c < DS; c++) {
        float s = st[c];
        aq += s * Wq[c * 128 + t];
        ak += s * Wk[c * 128 + t];
    }
    g_q[l * 128 + t] = aq;
    g_k[l * 128 + t] = ak;
}

// =====================================================================
// K2: attn[h,i,:] = softmax( mask( scaling * q_i . k_j ) )
// masked iff dist(i,j) > DISTBIN[h]/TRANS  (<=> sq > bin^2)
// grid=(512,4), block=256 (each thread handles j and j+256)
// =====================================================================
__global__ void attn_kernel(const float* __restrict__ Ca) {
    int i = blockIdx.x, h = blockIdx.y;
    int t = threadIdx.x;
    __shared__ float qv[DK];
    __shared__ float red[8];
    __shared__ float cai[3];
    if (t < DK) qv[t] = g_q[i * 128 + h * DK + t];
    if (t < 3)  cai[t] = Ca[i * 3 + t];
    __syncthreads();

    float bin = (float)(4 * (h + 1)) / 10.0f;
    float bin2 = bin * bin;
    const float scaling = 0.17677669529663687f;  // 1/sqrt(32)
    float cx = cai[0], cy = cai[1], cz = cai[2];

    float sc[2];
    #pragma unroll
    for (int u = 0; u < 2; u++) {
        int j = t + u * 256;
        float dx = Ca[3 * j] - cx, dy = Ca[3 * j + 1] - cy, dz = Ca[3 * j + 2] - cz;
        float sq = fmaxf(dx * dx + dy * dy + dz * dz, 1e-12f);
        if (sq > bin2) {
            sc[u] = NEGMAX;
        } else {
            float a = 0.0f;
            const float* kp = &g_k[j * 128 + h * DK];
            #pragma unroll
            for (int d = 0; d < DK; d++) a += qv[d] * kp[d];
            sc[u] = a * scaling;
        }
    }
    // block max
    float mx = fmaxf(sc[0], sc[1]);
    #pragma unroll
    for (int o = 16; o; o >>= 1) mx = fmaxf(mx, __shfl_xor_sync(0xffffffffu, mx, o));
    if ((t & 31) == 0) red[t >> 5] = mx;
    __syncthreads();
    mx = red[0];
    #pragma unroll
    for (int w = 1; w < 8; w++) mx = fmaxf(mx, red[w]);

    float e0 = expf(sc[0] - mx);
    float e1 = expf(sc[1] - mx);
    float ss = e0 + e1;
    #pragma unroll
    for (int o = 16; o; o >>= 1) ss += __shfl_xor_sync(0xffffffffu, ss, o);
    __syncthreads();                       // protect red before rewrite
    if ((t & 31) == 0) red[t >> 5] = ss;
    __syncthreads();
    ss = red[0];
    #pragma unroll
    for (int w = 1; w < 8; w++) ss += red[w];
    float inv = 1.0f / ss;

    float* ap = g_attn + ((size_t)h * L + i) * L;
    ap[t] = e0 * inv;
    ap[t + 256] = e1 * inv;
}

// =====================================================================
// K3: v = LN(msa)@Wv + bv, written transposed per head: g_vT[h][j][n*16+d]
// block=256 (8 warps, 1 row each), Wv in smem. grid=2048 -> 8 rows/warp
// =====================================================================
__global__ void v_kernel(const float* __restrict__ msa,
                         const float* __restrict__ n1g, const float* __restrict__ n1b,
                         const float* __restrict__ Wv, const float* __restrict__ bv) {
    __shared__ float sW[DM * DM];
    __shared__ float sbv[DM], sg[DM], sb[DM];
    __shared__ float lnb[8][DM];
    int t = threadIdx.x;
    for (int i = t; i < DM * DM; i += 256) sW[i] = Wv[i];
    if (t < DM) { sbv[t] = bv[t]; sg[t] = n1g[t]; sb[t] = n1b[t]; }
    __syncthreads();
    int w = t >> 5, lane = t & 31;
    for (int row = blockIdx.x * 8 + w; row < NROWS; row += gridDim.x * 8) {
        float2 x2 = ((const float2*)(msa + (size_t)row * DM))[lane];
        float s = x2.x + x2.y;
        #pragma unroll
        for (int o = 16; o; o >>= 1) s += __shfl_xor_sync(0xffffffffu, s, o);
        float m = s * (1.0f / DM);
        float d0 = x2.x - m, d1 = x2.y - m;
        float vv = d0 * d0 + d1 * d1;
        #pragma unroll
        for (int o = 16; o; o >>= 1) vv += __shfl_xor_sync(0xffffffffu, vv, o);
        float r = rsqrtf(vv * (1.0f / DM) + EPSLN);
        lnb[w][2 * lane]     = d0 * r * sg[2 * lane]     + sb[2 * lane];
        lnb[w][2 * lane + 1] = d1 * r * sg[2 * lane + 1] + sb[2 * lane + 1];
        __syncwarp();
        float a0 = sbv[lane], a1 = sbv[lane + 32];
        #pragma unroll
        for (int c = 0; c < DM; c++) {
            float lv = lnb[w][c];
            a0 += lv * sW[c * DM + lane];
            a1 += lv * sW[c * DM + lane + 32];
        }
        int n = row >> 9, j = row & 511;
        int c0 = lane, c1 = lane + 32;
        g_vT[(((size_t)(c0 >> 4) * L + j) * (NSEQ * DV)) + n * DV + (c0 & 15)] = a0;
        g_vT[(((size_t)(c1 >> 4) * L + j) * (NSEQ * DV)) + n * DV + (c1 & 15)] = a1;
        __syncwarp();
    }
}

// =====================================================================
// K4: per-head SGEMM: C_h(512 x 4096) = attn_h(512x512) @ vT_h(512x4096)
// scatter C into g_attout[(n*512+i)*64 + h*16+d].  64x64 tile, 4x4/thread
// grid=(64,8,4), block=256
// =====================================================================
__global__ void gemm_attn_kernel() {
    int h  = blockIdx.z;
    int n0 = blockIdx.x * 64;
    int m0 = blockIdx.y * 64;
    const float* __restrict__ A = g_attn + (size_t)h * L * L;
    const float* __restrict__ B = g_vT   + (size_t)h * L * (NSEQ * DV);
    __shared__ float As[16][68];
    __shared__ float Bs[16][68];
    int t = threadIdx.x;
    int tx = t & 15, ty = t >> 4;
    float acc[4][4];
    #pragma unroll
    for (int x = 0; x < 4; x++)
        #pragma unroll
        for (int y = 0; y < 4; y++) acc[x][y] = 0.0f;

    int ar = t >> 2, ac = (t & 3) * 4;
    int br = t >> 4, bc = (t & 15) * 4;

    for (int k0 = 0; k0 < L; k0 += 16) {
        float4 a4 = *(const float4*)(A + (size_t)(m0 + ar) * L + k0 + ac);
        float4 b4 = *(const float4*)(B + (size_t)(k0 + br) * (NSEQ * DV) + n0 + bc);
        As[ac][ar] = a4.x; As[ac + 1][ar] = a4.y; As[ac + 2][ar] = a4.z; As[ac + 3][ar] = a4.w;
        *(float4*)&Bs[br][bc] = b4;
        __syncthreads();
        #pragma unroll
        for (int kk = 0; kk < 16; kk++) {
            float4 av = *(const float4*)&As[kk][ty * 4];
            float4 bv = *(const float4*)&Bs[kk][tx * 4];
            acc[0][0] += av.x * bv.x; acc[0][1] += av.x * bv.y; acc[0][2] += av.x * bv.z; acc[0][3] += av.x * bv.w;
            acc[1][0] += av.y * bv.x; acc[1][1] += av.y * bv.y; acc[1][2] += av.y * bv.z; acc[1][3] += av.y * bv.w;
            acc[2][0] += av.z * bv.x; acc[2][1] += av.z * bv.y; acc[2][2] += av.z * bv.z; acc[2][3] += av.z * bv.w;
            acc[3][0] += av.w * bv.x; acc[3][1] += av.w * bv.y; acc[3][2] += av.w * bv.z; acc[3][3] += av.w * bv.w;
        }
        __syncthreads();
    }
    #pragma unroll
    for (int x = 0; x < 4; x++) {
        int i = m0 + ty * 4 + x;
        #pragma unroll
        for (int y = 0; y < 4; y++) {
            int col = n0 + tx * 4 + y;                 // = n*16 + d
            g_attout[((size_t)(col >> 4) * L + i) * DM + h * DV + (col & 15)] = acc[x][y];
        }
    }
}

// =====================================================================
// K5: msax = msa + attout@Wo + bo.  warp/row, Wo in smem. grid=1024, block=256
// =====================================================================
__global__ void oproj_kernel(const float* __restrict__ msa,
                             const float* __restrict__ Wo, const float* __restrict__ bo) {
    __shared__ float sW[DM * DM];
    __shared__ float sbo[DM];
    __shared__ float ob[8][DM];
    int t = threadIdx.x;
    for (int i = t; i < DM * DM; i += 256) sW[i] = Wo[i];
    if (t < DM) sbo[t] = bo[t];
    __syncthreads();
    int w = t >> 5, lane = t & 31;
    for (int row = blockIdx.x * 8 + w; row < NROWS; row += gridDim.x * 8) {
        float2 o2 = ((const float2*)(g_attout + (size_t)row * DM))[lane];
        ob[w][2 * lane] = o2.x; ob[w][2 * lane + 1] = o2.y;
        __syncwarp();
        float a0 = sbo[lane]      + msa[(size_t)row * DM + lane];
        float a1 = sbo[lane + 32] + msa[(size_t)row * DM + lane + 32];
        #pragma unroll
        for (int c = 0; c < DM; c++) {
            float lv = ob[w][c];
            a0 += lv * sW[c * DM + lane];
            a1 += lv * sW[c * DM + lane + 32];
        }
        g_msax[(size_t)row * DM + lane]      = a0;
        g_msax[(size_t)row * DM + lane + 32] = a1;
        __syncwarp();
    }
}

// =====================================================================
// K6: fused FF + final LN. W1,W2 resident in dyn smem; 4 rows / iteration.
// out = LN3( msax + relu(LN2(msax)@W1+b1)@W2 + b2 )
// =====================================================================
struct FFS {
    float W1[DM * FFH];      // 16384
    float W2[FFH * DM];      // 16384
    float b1[FFH];
    float b2[DM], g2[DM], bn2[DM], g3[DM], bn3[DM];
    float xb[4][DM];
    float ln2t[DM][4];       // [c][row]
    float h1t[FFH][4];       // [r][row]
    float part[4][FFH];
    float yb[4][DM];
};
extern __shared__ unsigned char ff_raw[];

__global__ void ff_kernel(const float* __restrict__ n2g, const float* __restrict__ n2b,
                          const float* __restrict__ W1, const float* __restrict__ b1,
                          const float* __restrict__ W2, const float* __restrict__ b2,
                          const float* __restrict__ n3g, const float* __restrict__ n3b,
                          float* __restrict__ out) {
    FFS* s = (FFS*)ff_raw;
    int t = threadIdx.x;
    for (int i = t; i < DM * FFH; i += 256) { s->W1[i] = W1[i]; s->W2[i] = W2[i]; }
    s->b1[t] = b1[t];
    if (t < DM) { s->b2[t] = b2[t]; s->g2[t] = n2g[t]; s->bn2[t] = n2b[t];
                  s->g3[t] = n3g[t]; s->bn3[t] = n3b[t]; }
    __syncthreads();
    int warp = t >> 5, lane = t & 31;
    const int nIter = NROWS / 4;
    for (int it = blockIdx.x; it < nIter; it += gridDim.x) {
        int row0 = it * 4;
        { int rr = t >> 6, c = t & 63; s->xb[rr][c] = g_msax[(size_t)(row0 + rr) * DM + c]; }
        __syncthreads();
        if (warp < 4) {               // LN2 (one warp per row)
            int rr = warp;
            float x0 = s->xb[rr][2 * lane], x1 = s->xb[rr][2 * lane + 1];
            float sum = x0 + x1;
            #pragma unroll
            for (int o = 16; o; o >>= 1) sum += __shfl_xor_sync(0xffffffffu, sum, o);
            float m = sum * (1.0f / DM);
            float d0 = x0 - m, d1 = x1 - m;
            float v = d0 * d0 + d1 * d1;
            #pragma unroll
            for (int o = 16; o; o >>= 1) v += __shfl_xor_sync(0xffffffffu, v, o);
            float r = rsqrtf(v * (1.0f / DM) + EPSLN);
            s->ln2t[2 * lane][rr]     = d0 * r * s->g2[2 * lane]     + s->bn2[2 * lane];
            s->ln2t[2 * lane + 1][rr] = d1 * r * s->g2[2 * lane + 1] + s->bn2[2 * lane + 1];
        }
        __syncthreads();
        {   // stage1: thread = hidden idx, all 4 rows
            float a0 = s->b1[t], a1 = a0, a2 = a0, a3 = a0;
            #pragma unroll 16
            for (int c = 0; c < DM; c++) {
                float w = s->W1[c * FFH + t];
                float4 lv = *(const float4*)&s->ln2t[c][0];
                a0 += lv.x * w; a1 += lv.y * w; a2 += lv.z * w; a3 += lv.w * w;
            }
            float4 hv = make_float4(fmaxf(a0, 0.f), fmaxf(a1, 0.f), fmaxf(a2, 0.f), fmaxf(a3, 0.f));
            *(float4*)&s->h1t[t][0] = hv;
        }
        __syncthreads();
        {   // stage2: thread = (g = r-chunk, o), partial sums for all 4 rows
            int g = t >> 6, o = t & 63;
            float a0 = 0, a1 = 0, a2 = 0, a3 = 0;
            #pragma unroll 16
            for (int r2 = 0; r2 < 64; r2++) {
                int rr2 = g * 64 + r2;
                float w = s->W2[rr2 * DM + o];
                float4 hv = *(const float4*)&s->h1t[rr2][0];
                a0 += hv.x * w; a1 += hv.y * w; a2 += hv.z * w; a3 += hv.w * w;
            }
            s->part[0][t] = a0; s->part[1][t] = a1; s->part[2][t] = a2; s->part[3][t] = a3;
        }
        __syncthreads();
        {   // combine partials + residual
            int rr = t >> 6, o = t & 63;
            float y = s->xb[rr][o] + s->b2[o]
                    + s->part[rr][o] + s->part[rr][64 + o]
                    + s->part[rr][128 + o] + s->part[rr][192 + o];
            s->yb[rr][o] = y;
        }
        __syncthreads();
        if (warp < 4) {               // LN3 + store
            int rr = warp;
            float y0 = s->yb[rr][2 * lane], y1 = s->yb[rr][2 * lane + 1];
            float sum = y0 + y1;
            #pragma unroll
            for (int o = 16; o; o >>= 1) sum += __shfl_xor_sync(0xffffffffu, sum, o);
            float m = sum * (1.0f / DM);
            float d0 = y0 - m, d1 = y1 - m;
            float v = d0 * d0 + d1 * d1;
            #pragma unroll
            for (int o = 16; o; o >>= 1) v += __shfl_xor_sync(0xffffffffu, v, o);
            float r = rsqrtf(v * (1.0f / DM) + EPSLN);
            size_t ob = (size_t)(row0 + rr) * DM;
            out[ob + 2 * lane]     = d0 * r * s->g3[2 * lane]     + s->bn3[2 * lane];
            out[ob + 2 * lane + 1] = d1 * r * s->g3[2 * lane + 1] + s->bn3[2 * lane + 1];
        }
        __syncthreads();
    }
}

// =====================================================================
extern "C" void kernel_launch(void* const* d_in, const int* in_sizes, int n_in,
                              void* d_out, int out_size) {
    const float* msa   = (const float*)d_in[0];
    const float* Ca    = (const float*)d_in[1];
    const float* state = (const float*)d_in[2];
    const float* ns_g  = (const float*)d_in[3];
    const float* ns_b  = (const float*)d_in[4];
    const float* n1_g  = (const float*)d_in[5];
    const float* n1_b  = (const float*)d_in[6];
    const float* Wq    = (const float*)d_in[7];
    const float* bq    = (const float*)d_in[8];
    const float* Wk    = (const float*)d_in[9];
    const float* bk    = (const float*)d_in[10];
    const float* Wv    = (const float*)d_in[11];
    const float* bv    = (const float*)d_in[12];
    const float* Wo    = (const float*)d_in[13];
    const float* bo    = (const float*)d_in[14];
    const float* n2_g  = (const float*)d_in[15];
    const float* n2_b  = (const float*)d_in[16];
    const float* W1    = (const float*)d_in[17];
    const float* b1    = (const float*)d_in[18];
    const float* W2    = (const float*)d_in[19];
    const float* b2    = (const float*)d_in[20];
    const float* n3_g  = (const float*)d_in[21];
    const float* n3_b  = (const float*)d_in[22];
    float* out = (float*)d_out;

    cudaFuncSetAttribute(ff_kernel, cudaFuncAttributeMaxDynamicSharedMemorySize,
                         (int)sizeof(FFS));

    qk_kernel<<<L, 128>>>(state, ns_g, ns_b, Wq, bq, Wk, bk);
    attn_kernel<<<dim3(L, NH), 256>>>(Ca);
    v_kernel<<<2048, 256>>>(msa, n1_g, n1_b, Wv, bv);
    gemm_attn_kernel<<<dim3(64, 8, 4), 256>>>();
    oproj_kernel<<<1024, 256>>>(msa, Wo, bo);
    ff_kernel<<<148, 256, sizeof(FFS)>>>(n2_g, n2_b, W1, b1, W2, b2, n3_g, n3_b, out);
}

// round 2
// speedup vs baseline: 1.7531x; 1.7531x over previous
#include <cuda_runtime.h>
#include <cuda_bf16.h>
#include <math.h>

// ---------------- problem constants ----------------
#define L 512
#define NSEQ 256
#define DM 64          // D_MSA
#define DS 32          // D_STATE
#define NH 4           // heads
#define DK 32
#define DV 16
#define FFH 256        // D_MSA * R_FF
#define NROWS (NSEQ * L)   // 131072
#define EPSLN 1e-5f
#define NEGMAX (-3.402823466e38f)

// ---------------- scratch (device globals: no runtime allocs) ----------------
__device__ float g_q[L * NH * DK];            // (l, h*32+d)
__device__ float g_k[L * NH * DK];
__device__ float g_attn[NH * L * L];          // (h, i, j)
__device__ float g_vT[NH * L * NSEQ * DV];    // (h, j, n*16+d)
__device__ float g_attout[NROWS * DM];        // (n*512+i, h*16+d)
__device__ float g_msax[NROWS * DM];          // msa + attn_out (post-residual)

// =====================================================================
// K1: st = LN(state); q = st@Wq+bq; k = st@Wk+bk.  grid=512, block=128
// =====================================================================
__global__ void qk_kernel(const float* __restrict__ state,
                          const float* __restrict__ nsg, const float* __restrict__ nsb,
                          const float* __restrict__ Wq, const float* __restrict__ bq,
                          const float* __restrict__ Wk, const float* __restrict__ bk) {
    int l = blockIdx.x;
    int t = threadIdx.x;                // 0..127
    __shared__ float st[DS];
    if (t < DS) {
        float x = state[l * DS + t];
        float s = x;
        #pragma unroll
        for (int o = 16; o; o >>= 1) s += __shfl_xor_sync(0xffffffffu, s, o);
        float m = s * (1.0f / DS);
        float d = x - m;
        float v = d * d;
        #pragma unroll
        for (int o = 16; o; o >>= 1) v += __shfl_xor_sync(0xffffffffu, v, o);
        float r = rsqrtf(v * (1.0f / DS) + EPSLN);
        st[t] = d * r * nsg[t] + nsb[t];
    }
    __syncthreads();
    float aq = bq[t], ak = bk[t];
    #pragma unroll
    for (int c = 0; c < DS; c++) {
        float s = st[c];
        aq += s * Wq[c * 128 + t];
        ak += s * Wk[c * 128 + t];
    }
    g_q[l * 128 + t] = aq;
    g_k[l * 128 + t] = ak;
}

// =====================================================================
// K2: attn[h,i,:] = softmax( mask( scaling * q_i . k_j ) )
// grid=(512,4), block=256
// =====================================================================
__global__ void attn_kernel(const float* __restrict__ Ca) {
    int i = blockIdx.x, h = blockIdx.y;
    int t = threadIdx.x;
    __shared__ float qv[DK];
    __shared__ float red[8];
    __shared__ float cai[3];
    if (t < DK) qv[t] = g_q[i * 128 + h * DK + t];
    if (t < 3)  cai[t] = Ca[i * 3 + t];
    __syncthreads();

    float bin = (float)(4 * (h + 1)) / 10.0f;
    float bin2 = bin * bin;
    const float scaling = 0.17677669529663687f;  // 1/sqrt(32)
    float cx = cai[0], cy = cai[1], cz = cai[2];

    float sc[2];
    #pragma unroll
    for (int u = 0; u < 2; u++) {
        int j = t + u * 256;
        float dx = Ca[3 * j] - cx, dy = Ca[3 * j + 1] - cy, dz = Ca[3 * j + 2] - cz;
        float sq = fmaxf(dx * dx + dy * dy + dz * dz, 1e-12f);
        if (sq > bin2) {
            sc[u] = NEGMAX;
        } else {
            float a = 0.0f;
            const float* kp = &g_k[j * 128 + h * DK];
            #pragma unroll
            for (int d = 0; d < DK; d++) a += qv[d] * kp[d];
            sc[u] = a * scaling;
        }
    }
    float mx = fmaxf(sc[0], sc[1]);
    #pragma unroll
    for (int o = 16; o; o >>= 1) mx = fmaxf(mx, __shfl_xor_sync(0xffffffffu, mx, o));
    if ((t & 31) == 0) red[t >> 5] = mx;
    __syncthreads();
    mx = red[0];
    #pragma unroll
    for (int w = 1; w < 8; w++) mx = fmaxf(mx, red[w]);

    float e0 = expf(sc[0] - mx);
    float e1 = expf(sc[1] - mx);
    float ss = e0 + e1;
    #pragma unroll
    for (int o = 16; o; o >>= 1) ss += __shfl_xor_sync(0xffffffffu, ss, o);
    __syncthreads();
    if ((t & 31) == 0) red[t >> 5] = ss;
    __syncthreads();
    ss = red[0];
    #pragma unroll
    for (int w = 1; w < 8; w++) ss += red[w];
    float inv = 1.0f / ss;

    float* ap = g_attn + ((size_t)h * L + i) * L;
    ap[t] = e0 * inv;
    ap[t + 256] = e1 * inv;
}

// =====================================================================
// K3: v = LN(msa)@Wv + bv, written transposed per head: g_vT[h][j][n*16+d]
// =====================================================================
__global__ void v_kernel(const float* __restrict__ msa,
                         const float* __restrict__ n1g, const float* __restrict__ n1b,
                         const float* __restrict__ Wv, const float* __restrict__ bv) {
    __shared__ float sW[DM * DM];
    __shared__ float sbv[DM], sg[DM], sb[DM];
    __shared__ float lnb[8][DM];
    int t = threadIdx.x;
    for (int i = t; i < DM * DM; i += 256) sW[i] = Wv[i];
    if (t < DM) { sbv[t] = bv[t]; sg[t] = n1g[t]; sb[t] = n1b[t]; }
    __syncthreads();
    int w = t >> 5, lane = t & 31;
    for (int row = blockIdx.x * 8 + w; row < NROWS; row += gridDim.x * 8) {
        float2 x2 = ((const float2*)(msa + (size_t)row * DM))[lane];
        float s = x2.x + x2.y;
        #pragma unroll
        for (int o = 16; o; o >>= 1) s += __shfl_xor_sync(0xffffffffu, s, o);
        float m = s * (1.0f / DM);
        float d0 = x2.x - m, d1 = x2.y - m;
        float vv = d0 * d0 + d1 * d1;
        #pragma unroll
        for (int o = 16; o; o >>= 1) vv += __shfl_xor_sync(0xffffffffu, vv, o);
        float r = rsqrtf(vv * (1.0f / DM) + EPSLN);
        lnb[w][2 * lane]     = d0 * r * sg[2 * lane]     + sb[2 * lane];
        lnb[w][2 * lane + 1] = d1 * r * sg[2 * lane + 1] + sb[2 * lane + 1];
        __syncwarp();
        float a0 = sbv[lane], a1 = sbv[lane + 32];
        #pragma unroll
        for (int c = 0; c < DM; c++) {
            float lv = lnb[w][c];
            a0 += lv * sW[c * DM + lane];
            a1 += lv * sW[c * DM + lane + 32];
        }
        int n = row >> 9, j = row & 511;
        int c0 = lane, c1 = lane + 32;
        g_vT[(((size_t)(c0 >> 4) * L + j) * (NSEQ * DV)) + n * DV + (c0 & 15)] = a0;
        g_vT[(((size_t)(c1 >> 4) * L + j) * (NSEQ * DV)) + n * DV + (c1 & 15)] = a1;
        __syncwarp();
    }
}

// =====================================================================
// K4: per-head SGEMM: C_h(512 x 4096) = attn_h(512x512) @ vT_h(512x4096)
// 128x128 tile, 8x8 microtile, k-chunk 16. grid=(32,4,4), block=256
// =====================================================================
__global__ void __launch_bounds__(256) gemm_attn_kernel() {
    int h  = blockIdx.z;
    int n0 = blockIdx.x * 128;
    int m0 = blockIdx.y * 128;
    const float* __restrict__ A = g_attn + (size_t)h * L * L;
    const float* __restrict__ B = g_vT   + (size_t)h * L * (NSEQ * DV);
    __shared__ float As[16][132];     // transposed [k][i]
    __shared__ float Bs[16][128];
    int t = threadIdx.x;
    int tx = t & 15, ty = t >> 4;

    float acc[8][8];
    #pragma unroll
    for (int x = 0; x < 8; x++)
        #pragma unroll
        for (int y = 0; y < 8; y++) acc[x][y] = 0.0f;

    for (int k0 = 0; k0 < L; k0 += 16) {
        // load A tile (128 rows x 16 k) -> transposed As[k][row]
        #pragma unroll
        for (int i = 0; i < 2; i++) {
            int f4 = t * 2 + i;                 // 0..511
            int row = f4 >> 2;                  // 0..127
            int kq  = f4 & 3;                   // k-quad
            float4 a4 = *(const float4*)(A + (size_t)(m0 + row) * L + k0 + kq * 4);
            As[kq * 4 + 0][row] = a4.x;
            As[kq * 4 + 1][row] = a4.y;
            As[kq * 4 + 2][row] = a4.z;
            As[kq * 4 + 3][row] = a4.w;
        }
        // load B tile (16 k x 128 cols)
        #pragma unroll
        for (int i = 0; i < 2; i++) {
            int f4 = t * 2 + i;                 // 0..511
            int r  = f4 >> 5;                   // 0..15
            int c4 = f4 & 31;                   // 0..31
            *(float4*)&Bs[r][c4 * 4] =
                *(const float4*)(B + (size_t)(k0 + r) * (NSEQ * DV) + n0 + c4 * 4);
        }
        __syncthreads();
        #pragma unroll
        for (int kk = 0; kk < 16; kk++) {
            float4 a0 = *(const float4*)&As[kk][ty * 4];
            float4 a1 = *(const float4*)&As[kk][ty * 4 + 64];
            float4 b0 = *(const float4*)&Bs[kk][tx * 4];
            float4 b1 = *(const float4*)&Bs[kk][tx * 4 + 64];
            float av[8] = {a0.x, a0.y, a0.z, a0.w, a1.x, a1.y, a1.z, a1.w};
            float bv[8] = {b0.x, b0.y, b0.z, b0.w, b1.x, b1.y, b1.z, b1.w};
            #pragma unroll
            for (int x = 0; x < 8; x++)
                #pragma unroll
                for (int y = 0; y < 8; y++) acc[x][y] += av[x] * bv[y];
        }
        __syncthreads();
    }
    // scatter: col = n*16+d -> g_attout[((col>>4)*L + i)*64 + h*16 + (col&15)]
    #pragma unroll
    for (int x = 0; x < 8; x++) {
        int i = m0 + ty * 4 + (x & 3) + (x >> 2) * 64;
        #pragma unroll
        for (int yh = 0; yh < 2; yh++) {
            int col = n0 + tx * 4 + yh * 64;        // multiple of 4, within one n
            int n = col >> 4, d0 = col & 15;
            float4 v4 = make_float4(acc[x][yh * 4], acc[x][yh * 4 + 1],
                                    acc[x][yh * 4 + 2], acc[x][yh * 4 + 3]);
            *(float4*)&g_attout[((size_t)n * L + i) * DM + h * DV + d0] = v4;
        }
    }
}

// =====================================================================
// K5: msax = msa + attout@Wo + bo.  warp/row, Wo in smem.
// =====================================================================
__global__ void oproj_kernel(const float* __restrict__ msa,
                             const float* __restrict__ Wo, const float* __restrict__ bo) {
    __shared__ float sW[DM * DM];
    __shared__ float sbo[DM];
    __shared__ float ob[8][DM];
    int t = threadIdx.x;
    for (int i = t; i < DM * DM; i += 256) sW[i] = Wo[i];
    if (t < DM) sbo[t] = bo[t];
    __syncthreads();
    int w = t >> 5, lane = t & 31;
    for (int row = blockIdx.x * 8 + w; row < NROWS; row += gridDim.x * 8) {
        float2 o2 = ((const float2*)(g_attout + (size_t)row * DM))[lane];
        ob[w][2 * lane] = o2.x; ob[w][2 * lane + 1] = o2.y;
        __syncwarp();
        float a0 = sbo[lane]      + msa[(size_t)row * DM + lane];
        float a1 = sbo[lane + 32] + msa[(size_t)row * DM + lane + 32];
        #pragma unroll
        for (int c = 0; c < DM; c++) {
            float lv = ob[w][c];
            a0 += lv * sW[c * DM + lane];
            a1 += lv * sW[c * DM + lane + 32];
        }
        g_msax[(size_t)row * DM + lane]      = a0;
        g_msax[(size_t)row * DM + lane + 32] = a1;
        __syncwarp();
    }
}

// =====================================================================
// K6: fused FF + final LN, register-blocked GEMM pipeline, 64-row tiles.
// out = LN3( msax + relu(LN2(msax)@W1+b1)@W2 + b2 )
// =====================================================================
struct FFS2 {
    float W1s[DM * FFH];     // [c][hid]   65536 B
    float W2s[FFH * DM];     // [r][o]     65536 B
    float b1s[FFH];
    float b2s[DM], g2[DM], bn2[DM], g3[DM], bn3[DM];
    float Xs[64 * DM];       // raw tile   16384 B
    float As[64 * DM];       // ln2 tile / y tile  16384 B
    float Hs[64 * FFH];      // relu H [row][hid]; reused as Ps[2][64][64]
};
extern __shared__ unsigned char ff_raw[];

__global__ void __launch_bounds__(256) ff_kernel(
        const float* __restrict__ n2g, const float* __restrict__ n2b,
        const float* __restrict__ W1, const float* __restrict__ b1,
        const float* __restrict__ W2, const float* __restrict__ b2,
        const float* __restrict__ n3g, const float* __restrict__ n3b,
        float* __restrict__ out) {
    FFS2* s = (FFS2*)ff_raw;
    int t = threadIdx.x;
    for (int i = t; i < DM * FFH; i += 256) { s->W1s[i] = W1[i]; s->W2s[i] = W2[i]; }
    s->b1s[t] = b1[t];
    if (t < DM) { s->b2s[t] = b2[t]; s->g2[t] = n2g[t]; s->bn2[t] = n2b[t];
                  s->g3[t] = n3g[t]; s->bn3[t] = n3b[t]; }
    __syncthreads();

    int warp = t >> 5, lane = t & 31;
    float* Ps = s->Hs;   // overlay after stage2

    const int nTiles = NROWS / 64;                     // 2048
    for (int tile = blockIdx.x; tile < nTiles; tile += gridDim.x) {
        size_t row0 = (size_t)tile * 64;
        // ---- load X tile (64x64), 4 float4 per thread ----
        #pragma unroll
        for (int i = 0; i < 4; i++) {
            int f4 = t * 4 + i;
            *(float4*)&s->Xs[f4 * 4] = *(const float4*)&g_msax[row0 * DM + f4 * 4];
        }
        __syncthreads();
        // ---- LN2: warp handles rows warp*8 .. +7 ----
        #pragma unroll
        for (int rr = 0; rr < 8; rr++) {
            int row = warp * 8 + rr;
            float2 x2 = *(const float2*)&s->Xs[row * DM + 2 * lane];
            float sum = x2.x + x2.y;
            #pragma unroll
            for (int o = 16; o; o >>= 1) sum += __shfl_xor_sync(0xffffffffu, sum, o);
            float m = sum * (1.0f / DM);
            float d0 = x2.x - m, d1 = x2.y - m;
            float vv = d0 * d0 + d1 * d1;
            #pragma unroll
            for (int o = 16; o; o >>= 1) vv += __shfl_xor_sync(0xffffffffu, vv, o);
            float r = rsqrtf(vv * (1.0f / DM) + EPSLN);
            s->As[row * DM + 2 * lane]     = d0 * r * s->g2[2 * lane]     + s->bn2[2 * lane];
            s->As[row * DM + 2 * lane + 1] = d1 * r * s->g2[2 * lane + 1] + s->bn2[2 * lane + 1];
        }
        __syncthreads();
        // ---- stage1: H(64x256) = relu(A @ W1 + b1); 8 rows x 8 hid per thread ----
        {
            int ry = t >> 5, hx = t & 31;
            int r0 = ry * 8;
            float acc[8][8];
            #pragma unroll
            for (int x = 0; x < 8; x++)
                #pragma unroll
                for (int y = 0; y < 8; y++) acc[x][y] = 0.0f;
            #pragma unroll 4
            for (int k0 = 0; k0 < DM; k0 += 4) {
                float4 av[8];
                #pragma unroll
                for (int r = 0; r < 8; r++)
                    av[r] = *(const float4*)&s->As[(r0 + r) * DM + k0];
                #pragma unroll
                for (int kk = 0; kk < 4; kk++) {
                    float4 w0 = *(const float4*)&s->W1s[(k0 + kk) * FFH + hx * 4];
                    float4 w1 = *(const float4*)&s->W1s[(k0 + kk) * FFH + 128 + hx * 4];
                    #pragma unroll
                    for (int r = 0; r < 8; r++) {
                        float a = (kk == 0) ? av[r].x : (kk == 1) ? av[r].y
                                 : (kk == 2) ? av[r].z : av[r].w;
                        acc[r][0] += a * w0.x; acc[r][1] += a * w0.y;
                        acc[r][2] += a * w0.z; acc[r][3] += a * w0.w;
                        acc[r][4] += a * w1.x; acc[r][5] += a * w1.y;
                        acc[r][6] += a * w1.z; acc[r][7] += a * w1.w;
                    }
                }
            }
            float4 blo = *(const float4*)&s->b1s[hx * 4];
            float4 bhi = *(const float4*)&s->b1s[128 + hx * 4];
            #pragma unroll
            for (int r = 0; r < 8; r++) {
                float4 h0 = make_float4(fmaxf(acc[r][0] + blo.x, 0.f),
                                        fmaxf(acc[r][1] + blo.y, 0.f),
                                        fmaxf(acc[r][2] + blo.z, 0.f),
                                        fmaxf(acc[r][3] + blo.w, 0.f));
                float4 h1 = make_float4(fmaxf(acc[r][4] + bhi.x, 0.f),
                                        fmaxf(acc[r][5] + bhi.y, 0.f),
                                        fmaxf(acc[r][6] + bhi.z, 0.f),
                                        fmaxf(acc[r][7] + bhi.w, 0.f));
                *(float4*)&s->Hs[(r0 + r) * FFH + hx * 4] = h0;
                *(float4*)&s->Hs[(r0 + r) * FFH + 128 + hx * 4] = h1;
            }
        }
        __syncthreads();
        // ---- stage2: Y(64x64) = H @ W2, k-split 2; 8 rows x 4 cols per thread ----
        float acc2[8][4];
        int kg, r20, c20;
        {
            kg = t >> 7;                 // 0/1 : k-half
            int sIdx = t & 127;
            int ry2 = sIdx >> 4, cx = sIdx & 15;
            r20 = ry2 * 8; c20 = cx * 4;
            #pragma unroll
            for (int x = 0; x < 8; x++)
                #pragma unroll
                for (int y = 0; y < 4; y++) acc2[x][y] = 0.0f;
            int kbase = kg * 128;
            #pragma unroll 4
            for (int k0 = 0; k0 < 128; k0 += 4) {
                float4 hv[8];
                #pragma unroll
                for (int r = 0; r < 8; r++)
                    hv[r] = *(const float4*)&s->Hs[(r20 + r) * FFH + kbase + k0];
                #pragma unroll
                for (int kk = 0; kk < 4; kk++) {
                    float4 w2v = *(const float4*)&s->W2s[(kbase + k0 + kk) * DM + c20];
                    #pragma unroll
                    for (int r = 0; r < 8; r++) {
                        float a = (kk == 0) ? hv[r].x : (kk == 1) ? hv[r].y
                                 : (kk == 2) ? hv[r].z : hv[r].w;
                        acc2[r][0] += a * w2v.x; acc2[r][1] += a * w2v.y;
                        acc2[r][2] += a * w2v.z; acc2[r][3] += a * w2v.w;
                    }
                }
            }
        }
        __syncthreads();                 // all H reads done -> safe to overlay Ps
        #pragma unroll
        for (int r = 0; r < 8; r++)
            *(float4*)&Ps[kg * 4096 + (r20 + r) * 64 + c20] =
                make_float4(acc2[r][0], acc2[r][1], acc2[r][2], acc2[r][3]);
        __syncthreads();
        // ---- combine + residual + b2 -> As (y tile) ----
        {
            int row = t >> 2, c0 = (t & 3) * 16;
            #pragma unroll
            for (int i = 0; i < 4; i++) {
                int c = c0 + i * 4;
                float4 xv = *(const float4*)&s->Xs[row * DM + c];
                float4 bv = *(const float4*)&s->b2s[c];
                float4 p0 = *(const float4*)&Ps[row * 64 + c];
                float4 p1 = *(const float4*)&Ps[4096 + row * 64 + c];
                *(float4*)&s->As[row * DM + c] =
                    make_float4(xv.x + bv.x + p0.x + p1.x,
                                xv.y + bv.y + p0.y + p1.y,
                                xv.z + bv.z + p0.z + p1.z,
                                xv.w + bv.w + p0.w + p1.w);
            }
        }
        __syncthreads();
        // ---- LN3 + store ----
        #pragma unroll
        for (int rr = 0; rr < 8; rr++) {
            int row = warp * 8 + rr;
            float2 y2 = *(const float2*)&s->As[row * DM + 2 * lane];
            float sum = y2.x + y2.y;
            #pragma unroll
            for (int o = 16; o; o >>= 1) sum += __shfl_xor_sync(0xffffffffu, sum, o);
            float m = sum * (1.0f / DM);
            float d0 = y2.x - m, d1 = y2.y - m;
            float vv = d0 * d0 + d1 * d1;
            #pragma unroll
            for (int o = 16; o; o >>= 1) vv += __shfl_xor_sync(0xffffffffu, vv, o);
            float r = rsqrtf(vv * (1.0f / DM) + EPSLN);
            size_t ob = (row0 + row) * DM;
            out[ob + 2 * lane]     = d0 * r * s->g3[2 * lane]     + s->bn3[2 * lane];
            out[ob + 2 * lane + 1] = d1 * r * s->g3[2 * lane + 1] + s->bn3[2 * lane + 1];
        }
        __syncthreads();                 // before next tile overwrites Xs/As/Hs
    }
}

// =====================================================================
extern "C" void kernel_launch(void* const* d_in, const int* in_sizes, int n_in,
                              void* d_out, int out_size) {
    const float* msa   = (const float*)d_in[0];
    const float* Ca    = (const float*)d_in[1];
    const float* state = (const float*)d_in[2];
    const float* ns_g  = (const float*)d_in[3];
    const float* ns_b  = (const float*)d_in[4];
    const float* n1_g  = (const float*)d_in[5];
    const float* n1_b  = (const float*)d_in[6];
    const float* Wq    = (const float*)d_in[7];
    const float* bq    = (const float*)d_in[8];
    const float* Wk    = (const float*)d_in[9];
    const float* bk    = (const float*)d_in[10];
    const float* Wv    = (const float*)d_in[11];
    const float* bv    = (const float*)d_in[12];
    const float* Wo    = (const float*)d_in[13];
    const float* bo    = (const float*)d_in[14];
    const float* n2_g  = (const float*)d_in[15];
    const float* n2_b  = (const float*)d_in[16];
    const float* W1    = (const float*)d_in[17];
    const float* b1    = (const float*)d_in[18];
    const float* W2    = (const float*)d_in[19];
    const float* b2    = (const float*)d_in[20];
    const float* n3_g  = (const float*)d_in[21];
    const float* n3_b  = (const float*)d_in[22];
    float* out = (float*)d_out;

    cudaFuncSetAttribute(ff_kernel, cudaFuncAttributeMaxDynamicSharedMemorySize,
                         (int)sizeof(FFS2));

    qk_kernel<<<L, 128>>>(state, ns_g, ns_b, Wq, bq, Wk, bk);
    attn_kernel<<<dim3(L, NH), 256>>>(Ca);
    v_kernel<<<2048, 256>>>(msa, n1_g, n1_b, Wv, bv);
    gemm_attn_kernel<<<dim3(32, 4, 4), 256>>>();
    oproj_kernel<<<1024, 256>>>(msa, Wo, bo);
    ff_kernel<<<148, 256, sizeof(FFS2)>>>(n2_g, n2_b, W1, b1, W2, b2, n3_g, n3_b, out);
}

// round 4
// speedup vs baseline: 1.9208x; 1.0957x over previous
#include <cuda_runtime.h>
#include <cuda_bf16.h>
#include <math.h>
#include <stdint.h>

// ---------------- problem constants ----------------
#define L 512
#define NSEQ 256
#define DM 64          // D_MSA
#define DS 32          // D_STATE
#define NH 4           // heads
#define DK 32
#define DV 16
#define FFH 256        // D_MSA * R_FF
#define NROWS (NSEQ * L)   // 131072
#define EPSLN 1e-5f
#define NEGMAX (-3.402823466e38f)

// ---------------- scratch (device globals: no runtime allocs) ----------------
__device__ float g_q[L * NH * DK];            // (l, h*32+d)
__device__ float g_k[L * NH * DK];
__device__ float g_attn[NH * L * L];          // (h, i, j)
__device__ float g_vT[NH * L * NSEQ * DV];    // (h, j, n*16+d)
__device__ float g_attout[NROWS * DM];        // (n*512+i, h*16+d)
__device__ float g_msax[NROWS * DM];          // msa + attn_out (post-residual)

// ---------------- mma.sync tf32 helper (valid on plain sm_100) -------
__device__ __forceinline__ void mma_tf32(float& c0, float& c1, float& c2, float& c3,
                                         uint32_t a0, uint32_t a1, uint32_t a2, uint32_t a3,
                                         uint32_t b0, uint32_t b1) {
    asm volatile(
        "mma.sync.aligned.m16n8k8.row.col.f32.tf32.tf32.f32 "
        "{%0,%1,%2,%3}, {%4,%5,%6,%7}, {%8,%9}, {%0,%1,%2,%3};"
        : "+f"(c0), "+f"(c1), "+f"(c2), "+f"(c3)
        : "r"(a0), "r"(a1), "r"(a2), "r"(a3), "r"(b0), "r"(b1));
}

// =====================================================================
// K1: st = LN(state); q = st@Wq+bq; k = st@Wk+bk.  grid=512, block=128
// =====================================================================
__global__ void qk_kernel(const float* __restrict__ state,
                          const float* __restrict__ nsg, const float* __restrict__ nsb,
                          const float* __restrict__ Wq, const float* __restrict__ bq,
                          const float* __restrict__ Wk, const float* __restrict__ bk) {
    int l = blockIdx.x;
    int t = threadIdx.x;                // 0..127
    __shared__ float st[DS];
    if (t < DS) {
        float x = state[l * DS + t];
        float s = x;
        #pragma unroll
        for (int o = 16; o; o >>= 1) s += __shfl_xor_sync(0xffffffffu, s, o);
        float m = s * (1.0f / DS);
        float d = x - m;
        float v = d * d;
        #pragma unroll
        for (int o = 16; o; o >>= 1) v += __shfl_xor_sync(0xffffffffu, v, o);
        float r = rsqrtf(v * (1.0f / DS) + EPSLN);
        st[t] = d * r * nsg[t] + nsb[t];
    }
    __syncthreads();
    float aq = bq[t], ak = bk[t];
    #pragma unroll
    for (int c = 0; c < DS; c++) {
        float s = st[c];
        aq += s * Wq[c * 128 + t];
        ak += s * Wk[c * 128 + t];
    }
    g_q[l * 128 + t] = aq;
    g_k[l * 128 + t] = ak;
}

// =====================================================================
// K2: attn[h,i,:] = softmax( mask( scaling * q_i . k_j ) )
// =====================================================================
__global__ void attn_kernel(const float* __restrict__ Ca) {
    int i = blockIdx.x, h = blockIdx.y;
    int t = threadIdx.x;
    __shared__ float qv[DK];
    __shared__ float red[8];
    __shared__ float cai[3];
    if (t < DK) qv[t] = g_q[i * 128 + h * DK + t];
    if (t < 3)  cai[t] = Ca[i * 3 + t];
    __syncthreads();

    float bin = (float)(4 * (h + 1)) / 10.0f;
    float bin2 = bin * bin;
    const float scaling = 0.17677669529663687f;  // 1/sqrt(32)
    float cx = cai[0], cy = cai[1], cz = cai[2];

    float sc[2];
    #pragma unroll
    for (int u = 0; u < 2; u++) {
        int j = t + u * 256;
        float dx = Ca[3 * j] - cx, dy = Ca[3 * j + 1] - cy, dz = Ca[3 * j + 2] - cz;
        float sq = fmaxf(dx * dx + dy * dy + dz * dz, 1e-12f);
        if (sq > bin2) {
            sc[u] = NEGMAX;
        } else {
            float a = 0.0f;
            const float* kp = &g_k[j * 128 + h * DK];
            #pragma unroll
            for (int d = 0; d < DK; d++) a += qv[d] * kp[d];
            sc[u] = a * scaling;
        }
    }
    float mx = fmaxf(sc[0], sc[1]);
    #pragma unroll
    for (int o = 16; o; o >>= 1) mx = fmaxf(mx, __shfl_xor_sync(0xffffffffu, mx, o));
    if ((t & 31) == 0) red[t >> 5] = mx;
    __syncthreads();
    mx = red[0];
    #pragma unroll
    for (int w = 1; w < 8; w++) mx = fmaxf(mx, red[w]);

    float e0 = expf(sc[0] - mx);
    float e1 = expf(sc[1] - mx);
    float ss = e0 + e1;
    #pragma unroll
    for (int o = 16; o; o >>= 1) ss += __shfl_xor_sync(0xffffffffu, ss, o);
    __syncthreads();
    if ((t & 31) == 0) red[t >> 5] = ss;
    __syncthreads();
    ss = red[0];
    #pragma unroll
    for (int w = 1; w < 8; w++) ss += red[w];
    float inv = 1.0f / ss;

    float* ap = g_attn + ((size_t)h * L + i) * L;
    ap[t] = e0 * inv;
    ap[t + 256] = e1 * inv;
}

// =====================================================================
// K3: v = LN(msa)@Wv + bv, written transposed per head: g_vT[h][j][n*16+d]
// =====================================================================
__global__ void v_kernel(const float* __restrict__ msa,
                         const float* __restrict__ n1g, const float* __restrict__ n1b,
                         const float* __restrict__ Wv, const float* __restrict__ bv) {
    __shared__ float sW[DM * DM];
    __shared__ float sbv[DM], sg[DM], sb[DM];
    __shared__ float lnb[8][DM];
    int t = threadIdx.x;
    for (int i = t; i < DM * DM; i += 256) sW[i] = Wv[i];
    if (t < DM) { sbv[t] = bv[t]; sg[t] = n1g[t]; sb[t] = n1b[t]; }
    __syncthreads();
    int w = t >> 5, lane = t & 31;
    for (int row = blockIdx.x * 8 + w; row < NROWS; row += gridDim.x * 8) {
        float2 x2 = ((const float2*)(msa + (size_t)row * DM))[lane];
        float s = x2.x + x2.y;
        #pragma unroll
        for (int o = 16; o; o >>= 1) s += __shfl_xor_sync(0xffffffffu, s, o);
        float m = s * (1.0f / DM);
        float d0 = x2.x - m, d1 = x2.y - m;
        float vv = d0 * d0 + d1 * d1;
        #pragma unroll
        for (int o = 16; o; o >>= 1) vv += __shfl_xor_sync(0xffffffffu, vv, o);
        float r = rsqrtf(vv * (1.0f / DM) + EPSLN);
        lnb[w][2 * lane]     = d0 * r * sg[2 * lane]     + sb[2 * lane];
        lnb[w][2 * lane + 1] = d1 * r * sg[2 * lane + 1] + sb[2 * lane + 1];
        __syncwarp();
        float a0 = sbv[lane], a1 = sbv[lane + 32];
        #pragma unroll
        for (int c = 0; c < DM; c++) {
            float lv = lnb[w][c];
            a0 += lv * sW[c * DM + lane];
            a1 += lv * sW[c * DM + lane + 32];
        }
        int n = row >> 9, j = row & 511;
        int c0 = lane, c1 = lane + 32;
        g_vT[(((size_t)(c0 >> 4) * L + j) * (NSEQ * DV)) + n * DV + (c0 & 15)] = a0;
        g_vT[(((size_t)(c1 >> 4) * L + j) * (NSEQ * DV)) + n * DV + (c1 & 15)] = a1;
        __syncwarp();
    }
}

// =====================================================================
// K4 (mma.sync tf32): per-head C(512x4096) = attn(512x512) @ vT(512x4096)
// CTA tile 128x128, 8 warps each 64x32 (4x4 of m16n8k8), K chunks of 32.
// smem holds fragments pre-permuted -> conflict-free LDS.128/LDS.64.
// grid=(32,4,4), block=256.
// =====================================================================
__global__ void __launch_bounds__(256, 2) gemm_attn_mma() {
    int h  = blockIdx.z;
    int n0 = blockIdx.x * 128;
    int i0 = blockIdx.y * 128;
    const float* __restrict__ A = g_attn + (size_t)h * L * L;
    const float* __restrict__ B = g_vT   + (size_t)h * L * (NSEQ * DV);

    // sA[(mt*4+ks)*128 + lane*4 + reg]   (mt 0..7, ks 0..3)
    // sB[(nt*4+ks)*64  + lane*2 + reg]   (nt 0..15)
    __shared__ float sA[4096];
    __shared__ float sB[4096];

    int t = threadIdx.x, wid = t >> 5, lid = t & 31;
    int wm = wid >> 2, wn = wid & 3;       // warp tile: rows wm*64, cols wn*32

    float acc[4][4][4];
    #pragma unroll
    for (int x = 0; x < 4; x++)
        #pragma unroll
        for (int y = 0; y < 4; y++)
            #pragma unroll
            for (int r = 0; r < 4; r++) acc[x][y][r] = 0.0f;

    for (int kc = 0; kc < 16; kc++) {
        int kc0 = kc * 32;
        // ---- A tile: 128 rows x 32 k -> fragment-permuted ----
        #pragma unroll
        for (int u = 0; u < 4; u++) {
            int id = t * 4 + u;                 // 0..1023
            int row = id >> 3, c4 = id & 7;     // k = c4*4 + e
            float4 v = *(const float4*)(A + (size_t)(i0 + row) * L + kc0 + c4 * 4);
            int mt = row >> 4, g = row & 15;
            int ks = c4 >> 1;
            int reg = ((g >= 8) ? 1 : 0) + ((c4 & 1) ? 2 : 0);
            int base = (mt * 4 + ks) * 128 + (g & 7) * 16 + reg;
            sA[base + 0]  = v.x;
            sA[base + 4]  = v.y;
            sA[base + 8]  = v.z;
            sA[base + 12] = v.w;
        }
        // ---- B tile: 32 k x 128 n -> fragment-permuted ----
        #pragma unroll
        for (int u = 0; u < 4; u++) {
            int id = t * 4 + u;                 // 0..1023
            int kr = id >> 5, n4 = id & 31;     // n = n4*4 + e
            float4 v = *(const float4*)(B + (size_t)(kc0 + kr) * (NSEQ * DV) + n0 + n4 * 4);
            int ks = kr >> 3, q = kr & 7;
            int reg = (q >= 4) ? 1 : 0;
            int nt = n4 >> 1;
            int gb = (n4 & 1) * 4;
            int base = (nt * 4 + ks) * 64 + (q & 3) * 2 + reg;
            sB[base + (gb + 0) * 8] = v.x;
            sB[base + (gb + 1) * 8] = v.y;
            sB[base + (gb + 2) * 8] = v.z;
            sB[base + (gb + 3) * 8] = v.w;
        }
        __syncthreads();
        // ---- compute: 4 k8-steps x (4 m-tiles x 4 n-tiles) ----
        #pragma unroll
        for (int ks = 0; ks < 4; ks++) {
            uint32_t bf[4][2];
            #pragma unroll
            for (int nt2 = 0; nt2 < 4; nt2++) {
                int nt = wn * 4 + nt2;
                float2 b2 = *(const float2*)&sB[(nt * 4 + ks) * 64 + lid * 2];
                bf[nt2][0] = __float_as_uint(b2.x);
                bf[nt2][1] = __float_as_uint(b2.y);
            }
            #pragma unroll
            for (int mt2 = 0; mt2 < 4; mt2++) {
                int mt = wm * 4 + mt2;
                float4 a4 = *(const float4*)&sA[(mt * 4 + ks) * 128 + lid * 4];
                uint32_t a0 = __float_as_uint(a4.x), a1 = __float_as_uint(a4.y);
                uint32_t a2 = __float_as_uint(a4.z), a3 = __float_as_uint(a4.w);
                #pragma unroll
                for (int nt2 = 0; nt2 < 4; nt2++)
                    mma_tf32(acc[mt2][nt2][0], acc[mt2][nt2][1],
                             acc[mt2][nt2][2], acc[mt2][nt2][3],
                             a0, a1, a2, a3, bf[nt2][0], bf[nt2][1]);
            }
        }
        __syncthreads();
    }

    // ---- epilogue: scatter into g_attout[(n*512+i)*64 + h*16+d] ----
    int g = lid >> 2, q2 = (lid & 3) * 2;
    #pragma unroll
    for (int mt2 = 0; mt2 < 4; mt2++) {
        int rowA = i0 + wm * 64 + mt2 * 16 + g;
        #pragma unroll
        for (int nt2 = 0; nt2 < 4; nt2++) {
            int col = n0 + wn * 32 + nt2 * 8 + q2;   // even -> d pair within n
            int n = col >> 4, d = col & 15;
            size_t base = ((size_t)n * L + rowA) * DM + h * DV + d;
            *(float2*)&g_attout[base] = make_float2(acc[mt2][nt2][0], acc[mt2][nt2][1]);
            *(float2*)&g_attout[base + 8 * DM] =
                make_float2(acc[mt2][nt2][2], acc[mt2][nt2][3]);
        }
    }
}

// =====================================================================
// K5: msax = msa + attout@Wo + bo.  warp/row, Wo in smem.
// =====================================================================
__global__ void oproj_kernel(const float* __restrict__ msa,
                             const float* __restrict__ Wo, const float* __restrict__ bo) {
    __shared__ float sW[DM * DM];
    __shared__ float sbo[DM];
    __shared__ float ob[8][DM];
    int t = threadIdx.x;
    for (int i = t; i < DM * DM; i += 256) sW[i] = Wo[i];
    if (t < DM) sbo[t] = bo[t];
    __syncthreads();
    int w = t >> 5, lane = t & 31;
    for (int row = blockIdx.x * 8 + w; row < NROWS; row += gridDim.x * 8) {
        float2 o2 = ((const float2*)(g_attout + (size_t)row * DM))[lane];
        ob[w][2 * lane] = o2.x; ob[w][2 * lane + 1] = o2.y;
        __syncwarp();
        float a0 = sbo[lane]      + msa[(size_t)row * DM + lane];
        float a1 = sbo[lane + 32] + msa[(size_t)row * DM + lane + 32];
        #pragma unroll
        for (int c = 0; c < DM; c++) {
            float lv = ob[w][c];
            a0 += lv * sW[c * DM + lane];
            a1 += lv * sW[c * DM + lane + 32];
        }
        g_msax[(size_t)row * DM + lane]      = a0;
        g_msax[(size_t)row * DM + lane + 32] = a1;
        __syncwarp();
    }
}

// =====================================================================
// K6: fused FF + final LN, register-blocked GEMM pipeline, 64-row tiles.
// =====================================================================
struct FFS2 {
    float W1s[DM * FFH];
    float W2s[FFH * DM];
    float b1s[FFH];
    float b2s[DM], g2[DM], bn2[DM], g3[DM], bn3[DM];
    float Xs[64 * DM];
    float As[64 * DM];
    float Hs[64 * FFH];
};
extern __shared__ unsigned char ff_raw[];

__global__ void __launch_bounds__(256) ff_kernel(
        const float* __restrict__ n2g, const float* __restrict__ n2b,
        const float* __restrict__ W1, const float* __restrict__ b1,
        const float* __restrict__ W2, const float* __restrict__ b2,
        const float* __restrict__ n3g, const float* __restrict__ n3b,
        float* __restrict__ out) {
    FFS2* s = (FFS2*)ff_raw;
    int t = threadIdx.x;
    for (int i = t; i < DM * FFH; i += 256) { s->W1s[i] = W1[i]; s->W2s[i] = W2[i]; }
    s->b1s[t] = b1[t];
    if (t < DM) { s->b2s[t] = b2[t]; s->g2[t] = n2g[t]; s->bn2[t] = n2b[t];
                  s->g3[t] = n3g[t]; s->bn3[t] = n3b[t]; }
    __syncthreads();

    int warp = t >> 5, lane = t & 31;
    float* Ps = s->Hs;

    const int nTiles = NROWS / 64;
    for (int tile = blockIdx.x; tile < nTiles; tile += gridDim.x) {
        size_t row0 = (size_t)tile * 64;
        #pragma unroll
        for (int i = 0; i < 4; i++) {
            int f4 = t * 4 + i;
            *(float4*)&s->Xs[f4 * 4] = *(const float4*)&g_msax[row0 * DM + f4 * 4];
        }
        __syncthreads();
        #pragma unroll
        for (int rr = 0; rr < 8; rr++) {
            int row = warp * 8 + rr;
            float2 x2 = *(const float2*)&s->Xs[row * DM + 2 * lane];
            float sum = x2.x + x2.y;
            #pragma unroll
            for (int o = 16; o; o >>= 1) sum += __shfl_xor_sync(0xffffffffu, sum, o);
            float m = sum * (1.0f / DM);
            float d0 = x2.x - m, d1 = x2.y - m;
            float vv = d0 * d0 + d1 * d1;
            #pragma unroll
            for (int o = 16; o; o >>= 1) vv += __shfl_xor_sync(0xffffffffu, vv, o);
            float r = rsqrtf(vv * (1.0f / DM) + EPSLN);
            s->As[row * DM + 2 * lane]     = d0 * r * s->g2[2 * lane]     + s->bn2[2 * lane];
            s->As[row * DM + 2 * lane + 1] = d1 * r * s->g2[2 * lane + 1] + s->bn2[2 * lane + 1];
        }
        __syncthreads();
        {
            int ry = t >> 5, hx = t & 31;
            int r0 = ry * 8;
            float acc[8][8];
            #pragma unroll
            for (int x = 0; x < 8; x++)
                #pragma unroll
                for (int y = 0; y < 8; y++) acc[x][y] = 0.0f;
            #pragma unroll 4
            for (int k0 = 0; k0 < DM; k0 += 4) {
                float4 av[8];
                #pragma unroll
                for (int r = 0; r < 8; r++)
                    av[r] = *(const float4*)&s->As[(r0 + r) * DM + k0];
                #pragma unroll
                for (int kk = 0; kk < 4; kk++) {
                    float4 w0 = *(const float4*)&s->W1s[(k0 + kk) * FFH + hx * 4];
                    float4 w1 = *(const float4*)&s->W1s[(k0 + kk) * FFH + 128 + hx * 4];
                    #pragma unroll
                    for (int r = 0; r < 8; r++) {
                        float a = (kk == 0) ? av[r].x : (kk == 1) ? av[r].y
                                 : (kk == 2) ? av[r].z : av[r].w;
                        acc[r][0] += a * w0.x; acc[r][1] += a * w0.y;
                        acc[r][2] += a * w0.z; acc[r][3] += a * w0.w;
                        acc[r][4] += a * w1.x; acc[r][5] += a * w1.y;
                        acc[r][6] += a * w1.z; acc[r][7] += a * w1.w;
                    }
                }
            }
            float4 blo = *(const float4*)&s->b1s[hx * 4];
            float4 bhi = *(const float4*)&s->b1s[128 + hx * 4];
            #pragma unroll
            for (int r = 0; r < 8; r++) {
                float4 h0 = make_float4(fmaxf(acc[r][0] + blo.x, 0.f),
                                        fmaxf(acc[r][1] + blo.y, 0.f),
                                        fmaxf(acc[r][2] + blo.z, 0.f),
                                        fmaxf(acc[r][3] + blo.w, 0.f));
                float4 h1 = make_float4(fmaxf(acc[r][4] + bhi.x, 0.f),
                                        fmaxf(acc[r][5] + bhi.y, 0.f),
                                        fmaxf(acc[r][6] + bhi.z, 0.f),
                                        fmaxf(acc[r][7] + bhi.w, 0.f));
                *(float4*)&s->Hs[(r0 + r) * FFH + hx * 4] = h0;
                *(float4*)&s->Hs[(r0 + r) * FFH + 128 + hx * 4] = h1;
            }
        }
        __syncthreads();
        float acc2[8][4];
        int kg, r20, c20;
        {
            kg = t >> 7;
            int sIdx = t & 127;
            int ry2 = sIdx >> 4, cx = sIdx & 15;
            r20 = ry2 * 8; c20 = cx * 4;
            #pragma unroll
            for (int x = 0; x < 8; x++)
                #pragma unroll
                for (int y = 0; y < 4; y++) acc2[x][y] = 0.0f;
            int kbase = kg * 128;
            #pragma unroll 4
            for (int k0 = 0; k0 < 128; k0 += 4) {
                float4 hv[8];
                #pragma unroll
                for (int r = 0; r < 8; r++)
                    hv[r] = *(const float4*)&s->Hs[(r20 + r) * FFH + kbase + k0];
                #pragma unroll
                for (int kk = 0; kk < 4; kk++) {
                    float4 w2v = *(const float4*)&s->W2s[(kbase + k0 + kk) * DM + c20];
                    #pragma unroll
                    for (int r = 0; r < 8; r++) {
                        float a = (kk == 0) ? hv[r].x : (kk == 1) ? hv[r].y
                                 : (kk == 2) ? hv[r].z : hv[r].w;
                        acc2[r][0] += a * w2v.x; acc2[r][1] += a * w2v.y;
                        acc2[r][2] += a * w2v.z; acc2[r][3] += a * w2v.w;
                    }
                }
            }
        }
        __syncthreads();
        #pragma unroll
        for (int r = 0; r < 8; r++)
            *(float4*)&Ps[kg * 4096 + (r20 + r) * 64 + c20] =
                make_float4(acc2[r][0], acc2[r][1], acc2[r][2], acc2[r][3]);
        __syncthreads();
        {
            int row = t >> 2, c0 = (t & 3) * 16;
            #pragma unroll
            for (int i = 0; i < 4; i++) {
                int c = c0 + i * 4;
                float4 xv = *(const float4*)&s->Xs[row * DM + c];
                float4 bv = *(const float4*)&s->b2s[c];
                float4 p0 = *(const float4*)&Ps[row * 64 + c];
                float4 p1 = *(const float4*)&Ps[4096 + row * 64 + c];
                *(float4*)&s->As[row * DM + c] =
                    make_float4(xv.x + bv.x + p0.x + p1.x,
                                xv.y + bv.y + p0.y + p1.y,
                                xv.z + bv.z + p0.z + p1.z,
                                xv.w + bv.w + p0.w + p1.w);
            }
        }
        __syncthreads();
        #pragma unroll
        for (int rr = 0; rr < 8; rr++) {
            int row = warp * 8 + rr;
            float2 y2 = *(const float2*)&s->As[row * DM + 2 * lane];
            float sum = y2.x + y2.y;
            #pragma unroll
            for (int o = 16; o; o >>= 1) sum += __shfl_xor_sync(0xffffffffu, sum, o);
            float m = sum * (1.0f / DM);
            float d0 = y2.x - m, d1 = y2.y - m;
            float vv = d0 * d0 + d1 * d1;
            #pragma unroll
            for (int o = 16; o; o >>= 1) vv += __shfl_xor_sync(0xffffffffu, vv, o);
            float r = rsqrtf(vv * (1.0f / DM) + EPSLN);
            size_t ob = (row0 + row) * DM;
            out[ob + 2 * lane]     = d0 * r * s->g3[2 * lane]     + s->bn3[2 * lane];
            out[ob + 2 * lane + 1] = d1 * r * s->g3[2 * lane + 1] + s->bn3[2 * lane + 1];
        }
        __syncthreads();
    }
}

// =====================================================================
extern "C" void kernel_launch(void* const* d_in, const int* in_sizes, int n_in,
                              void* d_out, int out_size) {
    const float* msa   = (const float*)d_in[0];
    const float* Ca    = (const float*)d_in[1];
    const float* state = (const float*)d_in[2];
    const float* ns_g  = (const float*)d_in[3];
    const float* ns_b  = (const float*)d_in[4];
    const float* n1_g  = (const float*)d_in[5];
    const float* n1_b  = (const float*)d_in[6];
    const float* Wq    = (const float*)d_in[7];
    const float* bq    = (const float*)d_in[8];
    const float* Wk    = (const float*)d_in[9];
    const float* bk    = (const float*)d_in[10];
    const float* Wv    = (const float*)d_in[11];
    const float* bv    = (const float*)d_in[12];
    const float* Wo    = (const float*)d_in[13];
    const float* bo    = (const float*)d_in[14];
    const float* n2_g  = (const float*)d_in[15];
    const float* n2_b  = (const float*)d_in[16];
    const float* W1    = (const float*)d_in[17];
    const float* b1    = (const float*)d_in[18];
    const float* W2    = (const float*)d_in[19];
    const float* b2    = (const float*)d_in[20];
    const float* n3_g  = (const float*)d_in[21];
    const float* n3_b  = (const float*)d_in[22];
    float* out = (float*)d_out;

    cudaFuncSetAttribute(ff_kernel, cudaFuncAttributeMaxDynamicSharedMemorySize,
                         (int)sizeof(FFS2));

    qk_kernel<<<L, 128>>>(state, ns_g, ns_b, Wq, bq, Wk, bk);
    attn_kernel<<<dim3(L, NH), 256>>>(Ca);
    v_kernel<<<2048, 256>>>(msa, n1_g, n1_b, Wv, bv);
    gemm_attn_mma<<<dim3(32, 4, 4), 256>>>();
    oproj_kernel<<<1024, 256>>>(msa, Wo, bo);
    ff_kernel<<<148, 256, sizeof(FFS2)>>>(n2_g, n2_b, W1, b1, W2, b2, n3_g, n3_b, out);
}

// round 5
// speedup vs baseline: 2.5755x; 1.3409x over previous
#include <cuda_runtime.h>
#include <cuda_bf16.h>
#include <math.h>
#include <stdint.h>

// ---------------- problem constants ----------------
#define L 512
#define NSEQ 256
#define DM 64          // D_MSA
#define DS 32          // D_STATE
#define NH 4           // heads
#define DK 32
#define DV 16
#define FFH 256        // D_MSA * R_FF
#define NROWS (NSEQ * L)   // 131072
#define EPSLN 1e-5f
#define NEGMAX (-3.402823466e38f)

// ---------------- scratch (device globals: no runtime allocs) ----------------
__device__ float g_q[L * NH * DK];            // (l, h*32+d)
__device__ float g_k[L * NH * DK];
// g_attn: A-fragment-permuted: [h][iblk(4)][kc(16)][4096]
__device__ float g_attn[NH * L * L];
__device__ float g_vT[NH * L * NSEQ * DV];    // (h, j, n*16+d)
__device__ float g_attout[NROWS * DM];        // (n*512+i, h*16+d)
__device__ float g_msax[NROWS * DM];          // msa + attn_out (post-residual)

// ---------------- mma.sync tf32 helper (valid on plain sm_100) -------
__device__ __forceinline__ void mma_tf32(float& c0, float& c1, float& c2, float& c3,
                                         uint32_t a0, uint32_t a1, uint32_t a2, uint32_t a3,
                                         uint32_t b0, uint32_t b1) {
    asm volatile(
        "mma.sync.aligned.m16n8k8.row.col.f32.tf32.tf32.f32 "
        "{%0,%1,%2,%3}, {%4,%5,%6,%7}, {%8,%9}, {%0,%1,%2,%3};"
        : "+f"(c0), "+f"(c1), "+f"(c2), "+f"(c3)
        : "r"(a0), "r"(a1), "r"(a2), "r"(a3), "r"(b0), "r"(b1));
}
#define F2U(x) __float_as_uint(x)

// =====================================================================
// K1: st = LN(state); q = st@Wq+bq; k = st@Wk+bk.  grid=512, block=128
// =====================================================================
__global__ void qk_kernel(const float* __restrict__ state,
                          const float* __restrict__ nsg, const float* __restrict__ nsb,
                          const float* __restrict__ Wq, const float* __restrict__ bq,
                          const float* __restrict__ Wk, const float* __restrict__ bk) {
    int l = blockIdx.x;
    int t = threadIdx.x;                // 0..127
    __shared__ float st[DS];
    if (t < DS) {
        float x = state[l * DS + t];
        float s = x;
        #pragma unroll
        for (int o = 16; o; o >>= 1) s += __shfl_xor_sync(0xffffffffu, s, o);
        float m = s * (1.0f / DS);
        float d = x - m;
        float v = d * d;
        #pragma unroll
        for (int o = 16; o; o >>= 1) v += __shfl_xor_sync(0xffffffffu, v, o);
        float r = rsqrtf(v * (1.0f / DS) + EPSLN);
        st[t] = d * r * nsg[t] + nsb[t];
    }
    __syncthreads();
    float aq = bq[t], ak = bk[t];
    #pragma unroll
    for (int c = 0; c < DS; c++) {
        float s = st[c];
        aq += s * Wq[c * 128 + t];
        ak += s * Wk[c * 128 + t];
    }
    g_q[l * 128 + t] = aq;
    g_k[l * 128 + t] = ak;
}

// =====================================================================
// K2: attn softmax -> written A-fragment-permuted for the mma GEMM.
// element (i, j) of head h lands at:
//   [((h*4+iblk)*16+kc)*4096 + (mt*4+ks)*128 + (g&7)*16 + (g>>3)
//    + 2*(c4&1) + e*4]
// with iblk=i>>7, ib=i&127, mt=ib>>4, g=ib&15, kc=j>>5, c4=(j>>2)&7, e=j&3
// =====================================================================
__global__ void attn_kernel(const float* __restrict__ Ca) {
    int i = blockIdx.x, h = blockIdx.y;
    int t = threadIdx.x;
    __shared__ float qv[DK];
    __shared__ float red[8];
    __shared__ float cai[3];
    if (t < DK) qv[t] = g_q[i * 128 + h * DK + t];
    if (t < 3)  cai[t] = Ca[i * 3 + t];
    __syncthreads();

    float bin = (float)(4 * (h + 1)) / 10.0f;
    float bin2 = bin * bin;
    const float scaling = 0.17677669529663687f;  // 1/sqrt(32)
    float cx = cai[0], cy = cai[1], cz = cai[2];

    float sc[2];
    #pragma unroll
    for (int u = 0; u < 2; u++) {
        int j = t + u * 256;
        float dx = Ca[3 * j] - cx, dy = Ca[3 * j + 1] - cy, dz = Ca[3 * j + 2] - cz;
        float sq = fmaxf(dx * dx + dy * dy + dz * dz, 1e-12f);
        if (sq > bin2) {
            sc[u] = NEGMAX;
        } else {
            float a = 0.0f;
            const float* kp = &g_k[j * 128 + h * DK];
            #pragma unroll
            for (int d = 0; d < DK; d++) a += qv[d] * kp[d];
            sc[u] = a * scaling;
        }
    }
    float mx = fmaxf(sc[0], sc[1]);
    #pragma unroll
    for (int o = 16; o; o >>= 1) mx = fmaxf(mx, __shfl_xor_sync(0xffffffffu, mx, o));
    if ((t & 31) == 0) red[t >> 5] = mx;
    __syncthreads();
    mx = red[0];
    #pragma unroll
    for (int w = 1; w < 8; w++) mx = fmaxf(mx, red[w]);

    float e0 = expf(sc[0] - mx);
    float e1 = expf(sc[1] - mx);
    float ss = e0 + e1;
    #pragma unroll
    for (int o = 16; o; o >>= 1) ss += __shfl_xor_sync(0xffffffffu, ss, o);
    __syncthreads();
    if ((t & 31) == 0) red[t >> 5] = ss;
    __syncthreads();
    ss = red[0];
    #pragma unroll
    for (int w = 1; w < 8; w++) ss += red[w];
    float inv = 1.0f / ss;

    int iblk = i >> 7, ib = i & 127;
    int mt = ib >> 4, g = ib & 15;
    size_t blkbase = ((size_t)(h * 4 + iblk) * 16) * 4096;
    int rowpart = (mt * 4) * 128 + (g & 7) * 16 + ((g >> 3) & 1);
    float vals[2] = {e0 * inv, e1 * inv};
    #pragma unroll
    for (int u = 0; u < 2; u++) {
        int j = t + u * 256;
        int kc = j >> 5, c4 = (j >> 2) & 7, e = j & 3, ks = c4 >> 1;
        g_attn[blkbase + (size_t)kc * 4096 + rowpart + ks * 128
               + 2 * (c4 & 1) + e * 4] = vals[u];
    }
}

// =====================================================================
// K3: v = LN(msa)@Wv + bv, written transposed per head: g_vT[h][j][n*16+d]
// =====================================================================
__global__ void v_kernel(const float* __restrict__ msa,
                         const float* __restrict__ n1g, const float* __restrict__ n1b,
                         const float* __restrict__ Wv, const float* __restrict__ bv) {
    __shared__ float sW[DM * DM];
    __shared__ float sbv[DM], sg[DM], sb[DM];
    __shared__ float lnb[8][DM];
    int t = threadIdx.x;
    for (int i = t; i < DM * DM; i += 256) sW[i] = Wv[i];
    if (t < DM) { sbv[t] = bv[t]; sg[t] = n1g[t]; sb[t] = n1b[t]; }
    __syncthreads();
    int w = t >> 5, lane = t & 31;
    for (int row = blockIdx.x * 8 + w; row < NROWS; row += gridDim.x * 8) {
        float2 x2 = ((const float2*)(msa + (size_t)row * DM))[lane];
        float s = x2.x + x2.y;
        #pragma unroll
        for (int o = 16; o; o >>= 1) s += __shfl_xor_sync(0xffffffffu, s, o);
        float m = s * (1.0f / DM);
        float d0 = x2.x - m, d1 = x2.y - m;
        float vv = d0 * d0 + d1 * d1;
        #pragma unroll
        for (int o = 16; o; o >>= 1) vv += __shfl_xor_sync(0xffffffffu, vv, o);
        float r = rsqrtf(vv * (1.0f / DM) + EPSLN);
        lnb[w][2 * lane]     = d0 * r * sg[2 * lane]     + sb[2 * lane];
        lnb[w][2 * lane + 1] = d1 * r * sg[2 * lane + 1] + sb[2 * lane + 1];
        __syncwarp();
        float a0 = sbv[lane], a1 = sbv[lane + 32];
        #pragma unroll
        for (int c = 0; c < DM; c++) {
            float lv = lnb[w][c];
            a0 += lv * sW[c * DM + lane];
            a1 += lv * sW[c * DM + lane + 32];
        }
        int n = row >> 9, j = row & 511;
        int c0 = lane, c1 = lane + 32;
        g_vT[(((size_t)(c0 >> 4) * L + j) * (NSEQ * DV)) + n * DV + (c0 & 15)] = a0;
        g_vT[(((size_t)(c1 >> 4) * L + j) * (NSEQ * DV)) + n * DV + (c1 & 15)] = a1;
        __syncwarp();
    }
}

// =====================================================================
// K4 (mma.sync tf32): per-head C(512x4096) = attn(512x512) @ vT(512x4096)
// A arrives pre-permuted in gmem (STS.128 fill); B permuted in-kernel.
// grid=(32,4,4), block=256.
// =====================================================================
__global__ void __launch_bounds__(256, 2) gemm_attn_mma() {
    int h  = blockIdx.z;
    int n0 = blockIdx.x * 128;
    int i0 = blockIdx.y * 128;
    const float* __restrict__ Abase =
        g_attn + ((size_t)(h * 4 + blockIdx.y) * 16) * 4096;
    const float* __restrict__ B = g_vT + (size_t)h * L * (NSEQ * DV);

    __shared__ float sA[4096];
    __shared__ float sB[4096];

    int t = threadIdx.x, wid = t >> 5, lid = t & 31;
    int wm = wid >> 2, wn = wid & 3;

    float acc[4][4][4];
    #pragma unroll
    for (int x = 0; x < 4; x++)
        #pragma unroll
        for (int y = 0; y < 4; y++)
            #pragma unroll
            for (int r = 0; r < 4; r++) acc[x][y][r] = 0.0f;

    for (int kc = 0; kc < 16; kc++) {
        int kc0 = kc * 32;
        // ---- A tile: pre-permuted -> pure vector copy ----
        const float4* src = (const float4*)(Abase + (size_t)kc * 4096);
        #pragma unroll
        for (int u = 0; u < 4; u++) {
            int id = t + u * 256;
            *(float4*)&sA[id * 4] = src[id];
        }
        // ---- B tile: 32 k x 128 n -> fragment-permuted ----
        #pragma unroll
        for (int u = 0; u < 4; u++) {
            int id = t * 4 + u;
            int kr = id >> 5, n4 = id & 31;
            float4 v = *(const float4*)(B + (size_t)(kc0 + kr) * (NSEQ * DV) + n0 + n4 * 4);
            int ks = kr >> 3, q = kr & 7;
            int reg = (q >= 4) ? 1 : 0;
            int nt = n4 >> 1;
            int gb = (n4 & 1) * 4;
            int base = (nt * 4 + ks) * 64 + (q & 3) * 2 + reg;
            sB[base + (gb + 0) * 8] = v.x;
            sB[base + (gb + 1) * 8] = v.y;
            sB[base + (gb + 2) * 8] = v.z;
            sB[base + (gb + 3) * 8] = v.w;
        }
        __syncthreads();
        #pragma unroll
        for (int ks = 0; ks < 4; ks++) {
            uint32_t bf[4][2];
            #pragma unroll
            for (int nt2 = 0; nt2 < 4; nt2++) {
                int nt = wn * 4 + nt2;
                float2 b2 = *(const float2*)&sB[(nt * 4 + ks) * 64 + lid * 2];
                bf[nt2][0] = F2U(b2.x);
                bf[nt2][1] = F2U(b2.y);
            }
            #pragma unroll
            for (int mt2 = 0; mt2 < 4; mt2++) {
                int mt = wm * 4 + mt2;
                float4 a4 = *(const float4*)&sA[(mt * 4 + ks) * 128 + lid * 4];
                #pragma unroll
                for (int nt2 = 0; nt2 < 4; nt2++)
                    mma_tf32(acc[mt2][nt2][0], acc[mt2][nt2][1],
                             acc[mt2][nt2][2], acc[mt2][nt2][3],
                             F2U(a4.x), F2U(a4.y), F2U(a4.z), F2U(a4.w),
                             bf[nt2][0], bf[nt2][1]);
            }
        }
        __syncthreads();
    }

    int g = lid >> 2, q2 = (lid & 3) * 2;
    #pragma unroll
    for (int mt2 = 0; mt2 < 4; mt2++) {
        int rowA = i0 + wm * 64 + mt2 * 16 + g;
        #pragma unroll
        for (int nt2 = 0; nt2 < 4; nt2++) {
            int col = n0 + wn * 32 + nt2 * 8 + q2;
            int n = col >> 4, d = col & 15;
            size_t base = ((size_t)n * L + rowA) * DM + h * DV + d;
            *(float2*)&g_attout[base] = make_float2(acc[mt2][nt2][0], acc[mt2][nt2][1]);
            *(float2*)&g_attout[base + 8 * DM] =
                make_float2(acc[mt2][nt2][2], acc[mt2][nt2][3]);
        }
    }
}

// =====================================================================
// K5: msax = msa + attout@Wo + bo.  warp/row, Wo in smem.
// =====================================================================
__global__ void oproj_kernel(const float* __restrict__ msa,
                             const float* __restrict__ Wo, const float* __restrict__ bo) {
    __shared__ float sW[DM * DM];
    __shared__ float sbo[DM];
    __shared__ float ob[8][DM];
    int t = threadIdx.x;
    for (int i = t; i < DM * DM; i += 256) sW[i] = Wo[i];
    if (t < DM) sbo[t] = bo[t];
    __syncthreads();
    int w = t >> 5, lane = t & 31;
    for (int row = blockIdx.x * 8 + w; row < NROWS; row += gridDim.x * 8) {
        float2 o2 = ((const float2*)(g_attout + (size_t)row * DM))[lane];
        ob[w][2 * lane] = o2.x; ob[w][2 * lane + 1] = o2.y;
        __syncwarp();
        float a0 = sbo[lane]      + msa[(size_t)row * DM + lane];
        float a1 = sbo[lane + 32] + msa[(size_t)row * DM + lane + 32];
        #pragma unroll
        for (int c = 0; c < DM; c++) {
            float lv = ob[w][c];
            a0 += lv * sW[c * DM + lane];
            a1 += lv * sW[c * DM + lane + 32];
        }
        g_msax[(size_t)row * DM + lane]      = a0;
        g_msax[(size_t)row * DM + lane + 32] = a1;
        __syncwarp();
    }
}

// =====================================================================
// K6 (mma.sync tf32): fused FF + final LN, 64-row tiles.
// A-frag addr for (row r, k c) in M x K tile (KS8 = K/8):
//   (r>>4)*KS8+ (c>>3))*128 + (r&7)*16 + ((c&7)&3)*4 + ((r>>3)&1) + (((c>>2)&1)<<1)
// B-frag addr for (k c, col n):
//   ((n>>3)*KS8 + (c>>3))*64 + ((n&7)*4 + (c&3))*2 + ((c>>2)&1)
// =====================================================================
struct FFS3 {
    float W1p[DM * FFH];     // GEMM1 B-frags (KS8=8)
    float W2p[FFH * DM];     // GEMM2 B-frags (KS8=32)
    float b1s[FFH];
    float b2s[DM], g2[DM], bn2[DM], g3[DM], bn3[DM];
    float Xs[64 * DM];       // raw X tile
    float Ap[64 * DM];       // GEMM1 A-frags (KS8=8)
    float Hp[64 * FFH];      // GEMM2 A-frags (KS8=32); overlaid Ps[2][64][72]
};
extern __shared__ unsigned char ff_raw[];

__global__ void __launch_bounds__(256) ff_mma_kernel(
        const float* __restrict__ n2g, const float* __restrict__ n2b,
        const float* __restrict__ W1, const float* __restrict__ b1,
        const float* __restrict__ W2, const float* __restrict__ b2,
        const float* __restrict__ n3g, const float* __restrict__ n3b,
        float* __restrict__ out) {
    FFS3* s = (FFS3*)ff_raw;
    int t = threadIdx.x, warp = t >> 5, lane = t & 31;
    int rg = lane >> 2, q2 = (lane & 3) * 2;

    // one-time weight permutes
    for (int i = t; i < DM * FFH; i += 256) {        // W1[c][n], c<64, n<256
        int c = i >> 8, n = i & 255;
        s->W1p[((n >> 3) * 8 + (c >> 3)) * 64 + ((n & 7) * 4 + (c & 3)) * 2
               + ((c >> 2) & 1)] = W1[i];
    }
    for (int i = t; i < FFH * DM; i += 256) {        // W2[c][n], c<256, n<64
        int c = i >> 6, n = i & 63;
        s->W2p[((n >> 3) * 32 + (c >> 3)) * 64 + ((n & 7) * 4 + (c & 3)) * 2
               + ((c >> 2) & 1)] = W2[i];
    }
    s->b1s[t] = b1[t];
    if (t < DM) { s->b2s[t] = b2[t]; s->g2[t] = n2g[t]; s->bn2[t] = n2b[t];
                  s->g3[t] = n3g[t]; s->bn3[t] = n3b[t]; }
    __syncthreads();

    const int nTiles = NROWS / 64;                   // 2048
    for (int tile = blockIdx.x; tile < nTiles; tile += gridDim.x) {
        size_t row0 = (size_t)tile * 64;
        // ---- load X tile ----
        #pragma unroll
        for (int i = 0; i < 4; i++) {
            int f4 = t * 4 + i;
            *(float4*)&s->Xs[f4 * 4] = *(const float4*)&g_msax[row0 * DM + f4 * 4];
        }
        __syncthreads();
        // ---- LN2 -> Ap (A-frag permuted, KS8=8) ----
        #pragma unroll
        for (int rr = 0; rr < 8; rr++) {
            int row = warp * 8 + rr;
            float2 x2 = *(const float2*)&s->Xs[row * DM + 2 * lane];
            float sum = x2.x + x2.y;
            #pragma unroll
            for (int o = 16; o; o >>= 1) sum += __shfl_xor_sync(0xffffffffu, sum, o);
            float m = sum * (1.0f / DM);
            float d0 = x2.x - m, d1 = x2.y - m;
            float vv = d0 * d0 + d1 * d1;
            #pragma unroll
            for (int o = 16; o; o >>= 1) vv += __shfl_xor_sync(0xffffffffu, vv, o);
            float r = rsqrtf(vv * (1.0f / DM) + EPSLN);
            int c0 = 2 * lane;
            float v0 = d0 * r * s->g2[c0]     + s->bn2[c0];
            float v1 = d1 * r * s->g2[c0 + 1] + s->bn2[c0 + 1];
            int mt = row >> 4, g = row & 15;
            int base = (mt * 8 + (c0 >> 3)) * 128 + (g & 7) * 16 + ((g >> 3) & 1);
            int kk0 = c0 & 7;
            s->Ap[base + (kk0 & 3) * 4 + ((kk0 >> 2) << 1)]       = v0;
            s->Ap[base + ((kk0 + 1) & 3) * 4 + (((kk0 + 1) >> 2) << 1)] = v1;
        }
        __syncthreads();
        // ---- GEMM1: H(64x256) = relu(Ap @ W1 + b1) -> Hp (A-frag, KS8=32) ----
        {
            int wm = warp >> 2, wn = warp & 3;       // 2m x 4n
            float acc1[2][8][4];
            #pragma unroll
            for (int x = 0; x < 2; x++)
                #pragma unroll
                for (int y = 0; y < 8; y++)
                    #pragma unroll
                    for (int r = 0; r < 4; r++) acc1[x][y][r] = 0.0f;
            #pragma unroll
            for (int ks = 0; ks < 8; ks++) {
                float4 af0 = *(const float4*)&s->Ap[((wm * 2 + 0) * 8 + ks) * 128 + lane * 4];
                float4 af1 = *(const float4*)&s->Ap[((wm * 2 + 1) * 8 + ks) * 128 + lane * 4];
                #pragma unroll
                for (int nt = 0; nt < 8; nt++) {
                    float2 b2v = *(const float2*)&s->W1p[((wn * 8 + nt) * 8 + ks) * 64 + lane * 2];
                    mma_tf32(acc1[0][nt][0], acc1[0][nt][1], acc1[0][nt][2], acc1[0][nt][3],
                             F2U(af0.x), F2U(af0.y), F2U(af0.z), F2U(af0.w),
                             F2U(b2v.x), F2U(b2v.y));
                    mma_tf32(acc1[1][nt][0], acc1[1][nt][1], acc1[1][nt][2], acc1[1][nt][3],
                             F2U(af1.x), F2U(af1.y), F2U(af1.z), F2U(af1.w),
                             F2U(b2v.x), F2U(b2v.y));
                }
            }
            #pragma unroll
            for (int mt = 0; mt < 2; mt++) {
                int mt2 = wm * 2 + mt;
                #pragma unroll
                for (int nt = 0; nt < 8; nt++) {
                    int ks2 = wn * 8 + nt;
                    int c0 = ks2 * 8 + q2;
                    float b1a = s->b1s[c0], b1b = s->b1s[c0 + 1];
                    float v0 = fmaxf(acc1[mt][nt][0] + b1a, 0.f);
                    float v1 = fmaxf(acc1[mt][nt][1] + b1b, 0.f);
                    float v2 = fmaxf(acc1[mt][nt][2] + b1a, 0.f);
                    float v3 = fmaxf(acc1[mt][nt][3] + b1b, 0.f);
                    int fb = (mt2 * 32 + ks2) * 128 + rg * 16;
                    int a0 = fb + (q2 & 3) * 4 + ((q2 >> 2) << 1);
                    int kk1 = q2 + 1;
                    int a1 = fb + (kk1 & 3) * 4 + ((kk1 >> 2) << 1);
                    *(float2*)&s->Hp[a0] = make_float2(v0, v2);
                    *(float2*)&s->Hp[a1] = make_float2(v1, v3);
                }
            }
        }
        __syncthreads();
        // ---- GEMM2: Y(64x64) = Hp @ W2, k-split 2 ----
        {
            int kg = warp >> 2, wm2 = (warp >> 1) & 1, wn2 = warp & 1;
            float acc2[2][4][4];
            #pragma unroll
            for (int x = 0; x < 2; x++)
                #pragma unroll
                for (int y = 0; y < 4; y++)
                    #pragma unroll
                    for (int r = 0; r < 4; r++) acc2[x][y][r] = 0.0f;
            #pragma unroll 8
            for (int ks = 0; ks < 16; ks++) {
                int ksg = kg * 16 + ks;
                float4 af0 = *(const float4*)&s->Hp[((wm2 * 2 + 0) * 32 + ksg) * 128 + lane * 4];
                float4 af1 = *(const float4*)&s->Hp[((wm2 * 2 + 1) * 32 + ksg) * 128 + lane * 4];
                #pragma unroll
                for (int nt = 0; nt < 4; nt++) {
                    float2 b2v = *(const float2*)&s->W2p[((wn2 * 4 + nt) * 32 + ksg) * 64 + lane * 2];
                    mma_tf32(acc2[0][nt][0], acc2[0][nt][1], acc2[0][nt][2], acc2[0][nt][3],
                             F2U(af0.x), F2U(af0.y), F2U(af0.z), F2U(af0.w),
                             F2U(b2v.x), F2U(b2v.y));
                    mma_tf32(acc2[1][nt][0], acc2[1][nt][1], acc2[1][nt][2], acc2[1][nt][3],
                             F2U(af1.x), F2U(af1.y), F2U(af1.z), F2U(af1.w),
                             F2U(b2v.x), F2U(b2v.y));
                }
            }
            __syncthreads();                 // Hp reads done -> overlay Ps
            float* Ps = s->Hp;               // Ps[kg][64][72]
            #pragma unroll
            for (int mt = 0; mt < 2; mt++)
                #pragma unroll
                for (int nt = 0; nt < 4; nt++) {
                    int r0 = wm2 * 32 + mt * 16 + rg;
                    int c0 = wn2 * 32 + nt * 8 + q2;
                    *(float2*)&Ps[kg * 4608 + r0 * 72 + c0] =
                        make_float2(acc2[mt][nt][0], acc2[mt][nt][1]);
                    *(float2*)&Ps[kg * 4608 + (r0 + 8) * 72 + c0] =
                        make_float2(acc2[mt][nt][2], acc2[mt][nt][3]);
                }
        }
        __syncthreads();
        // ---- combine + residual + LN3 -> out ----
        {
            float* Ps = s->Hp;
            #pragma unroll
            for (int rr = 0; rr < 8; rr++) {
                int row = warp * 8 + rr;
                float2 x2 = *(const float2*)&s->Xs[row * DM + 2 * lane];
                float2 p0 = *(const float2*)&Ps[row * 72 + 2 * lane];
                float2 p1 = *(const float2*)&Ps[4608 + row * 72 + 2 * lane];
                float y0 = x2.x + s->b2s[2 * lane]     + p0.x + p1.x;
                float y1 = x2.y + s->b2s[2 * lane + 1] + p0.y + p1.y;
                float sum = y0 + y1;
                #pragma unroll
                for (int o = 16; o; o >>= 1) sum += __shfl_xor_sync(0xffffffffu, sum, o);
                float m = sum * (1.0f / DM);
                float d0 = y0 - m, d1 = y1 - m;
                float vv = d0 * d0 + d1 * d1;
                #pragma unroll
                for (int o = 16; o; o >>= 1) vv += __shfl_xor_sync(0xffffffffu, vv, o);
                float r = rsqrtf(vv * (1.0f / DM) + EPSLN);
                size_t ob = (row0 + row) * DM;
                out[ob + 2 * lane]     = d0 * r * s->g3[2 * lane]     + s->bn3[2 * lane];
                out[ob + 2 * lane + 1] = d1 * r * s->g3[2 * lane + 1] + s->bn3[2 * lane + 1];
            }
        }
        __syncthreads();
    }
}

// =====================================================================
extern "C" void kernel_launch(void* const* d_in, const int* in_sizes, int n_in,
                              void* d_out, int out_size) {
    const float* msa   = (const float*)d_in[0];
    const float* Ca    = (const float*)d_in[1];
    const float* state = (const float*)d_in[2];
    const float* ns_g  = (const float*)d_in[3];
    const float* ns_b  = (const float*)d_in[4];
    const float* n1_g  = (const float*)d_in[5];
    const float* n1_b  = (const float*)d_in[6];
    const float* Wq    = (const float*)d_in[7];
    const float* bq    = (const float*)d_in[8];
    const float* Wk    = (const float*)d_in[9];
    const float* bk    = (const float*)d_in[10];
    const float* Wv    = (const float*)d_in[11];
    const float* bv    = (const float*)d_in[12];
    const float* Wo    = (const float*)d_in[13];
    const float* bo    = (const float*)d_in[14];
    const float* n2_g  = (const float*)d_in[15];
    const float* n2_b  = (const float*)d_in[16];
    const float* W1    = (const float*)d_in[17];
    const float* b1    = (const float*)d_in[18];
    const float* W2    = (const float*)d_in[19];
    const float* b2    = (const float*)d_in[20];
    const float* n3_g  = (const float*)d_in[21];
    const float* n3_b  = (const float*)d_in[22];
    float* out = (float*)d_out;

    cudaFuncSetAttribute(ff_mma_kernel, cudaFuncAttributeMaxDynamicSharedMemorySize,
                         (int)sizeof(FFS3));

    qk_kernel<<<L, 128>>>(state, ns_g, ns_b, Wq, bq, Wk, bk);
    attn_kernel<<<dim3(L, NH), 256>>>(Ca);
    v_kernel<<<2048, 256>>>(msa, n1_g, n1_b, Wv, bv);
    gemm_attn_mma<<<dim3(32, 4, 4), 256>>>();
    oproj_kernel<<<1024, 256>>>(msa, Wo, bo);
    ff_mma_kernel<<<148, 256, sizeof(FFS3)>>>(n2_g, n2_b, W1, b1, W2, b2, n3_g, n3_b, out);
}

// round 6
// speedup vs baseline: 4.0149x; 1.5588x over previous
#include <cuda_runtime.h>
#include <cuda_bf16.h>
#include <math.h>
#include <stdint.h>

// ---------------- problem constants ----------------
#define L 512
#define NSEQ 256
#define DM 64          // D_MSA
#define DS 32          // D_STATE
#define NH 4           // heads
#define DK 32
#define DV 16
#define FFH 256        // D_MSA * R_FF
#define NROWS (NSEQ * L)   // 131072
#define EPSLN 1e-5f
#define NEGMAX (-3.402823466e38f)

// ---------------- scratch (device globals: no runtime allocs) ----------------
__device__ float g_q[L * NH * DK];            // (l, h*32+d)
__device__ float g_k[L * NH * DK];
// g_attn: A-fragment-permuted: [h][iblk(4)][kc(16)][4096]
__device__ float g_attn[NH * L * L];
// g_vT: B-fragment-permuted: [h][nblk(32)][kc(16)][4096]
__device__ float g_vT[NH * L * NSEQ * DV];
// g_attout: A-fragment-permuted 64-row tiles: [tile(2048)][4096]
__device__ float g_attout[NROWS * DM];
__device__ float g_msax[NROWS * DM];          // msa + attn_out (raw rows)

// ---------------- mma.sync tf32 helper (valid on plain sm_100) -------
__device__ __forceinline__ void mma_tf32(float& c0, float& c1, float& c2, float& c3,
                                         uint32_t a0, uint32_t a1, uint32_t a2, uint32_t a3,
                                         uint32_t b0, uint32_t b1) {
    asm volatile(
        "mma.sync.aligned.m16n8k8.row.col.f32.tf32.tf32.f32 "
        "{%0,%1,%2,%3}, {%4,%5,%6,%7}, {%8,%9}, {%0,%1,%2,%3};"
        : "+f"(c0), "+f"(c1), "+f"(c2), "+f"(c3)
        : "r"(a0), "r"(a1), "r"(a2), "r"(a3), "r"(b0), "r"(b1));
}
#define F2U(x) __float_as_uint(x)

// fragment address helpers (KS8 = K/8 of the tile)
__device__ __forceinline__ int afrag_addr(int r, int c, int KS8) {
    return ((r >> 4) * KS8 + (c >> 3)) * 128 + (r & 7) * 16 + ((r >> 3) & 1)
         + (c & 3) * 4 + ((c >> 2) & 1) * 2;
}
__device__ __forceinline__ int bfrag_addr(int c, int n, int KS8) {
    return ((n >> 3) * KS8 + (c >> 3)) * 64 + (n & 7) * 8 + (c & 3) * 2 + ((c >> 2) & 1);
}

// =====================================================================
// K1: st = LN(state); q = st@Wq+bq; k = st@Wk+bk.  grid=512, block=128
// =====================================================================
__global__ void qk_kernel(const float* __restrict__ state,
                          const float* __restrict__ nsg, const float* __restrict__ nsb,
                          const float* __restrict__ Wq, const float* __restrict__ bq,
                          const float* __restrict__ Wk, const float* __restrict__ bk) {
    int l = blockIdx.x;
    int t = threadIdx.x;                // 0..127
    __shared__ float st[DS];
    if (t < DS) {
        float x = state[l * DS + t];
        float s = x;
        #pragma unroll
        for (int o = 16; o; o >>= 1) s += __shfl_xor_sync(0xffffffffu, s, o);
        float m = s * (1.0f / DS);
        float d = x - m;
        float v = d * d;
        #pragma unroll
        for (int o = 16; o; o >>= 1) v += __shfl_xor_sync(0xffffffffu, v, o);
        float r = rsqrtf(v * (1.0f / DS) + EPSLN);
        st[t] = d * r * nsg[t] + nsb[t];
    }
    __syncthreads();
    float aq = bq[t], ak = bk[t];
    #pragma unroll
    for (int c = 0; c < DS; c++) {
        float s = st[c];
        aq += s * Wq[c * 128 + t];
        ak += s * Wk[c * 128 + t];
    }
    g_q[l * 128 + t] = aq;
    g_k[l * 128 + t] = ak;
}

// =====================================================================
// K2: attn softmax -> A-fragment-permuted gmem (validated R5 layout)
// =====================================================================
__global__ void attn_kernel(const float* __restrict__ Ca) {
    int i = blockIdx.x, h = blockIdx.y;
    int t = threadIdx.x;
    __shared__ float qv[DK];
    __shared__ float red[8];
    __shared__ float cai[3];
    if (t < DK) qv[t] = g_q[i * 128 + h * DK + t];
    if (t < 3)  cai[t] = Ca[i * 3 + t];
    __syncthreads();

    float bin = (float)(4 * (h + 1)) / 10.0f;
    float bin2 = bin * bin;
    const float scaling = 0.17677669529663687f;  // 1/sqrt(32)
    float cx = cai[0], cy = cai[1], cz = cai[2];

    float sc[2];
    #pragma unroll
    for (int u = 0; u < 2; u++) {
        int j = t + u * 256;
        float dx = Ca[3 * j] - cx, dy = Ca[3 * j + 1] - cy, dz = Ca[3 * j + 2] - cz;
        float sq = fmaxf(dx * dx + dy * dy + dz * dz, 1e-12f);
        if (sq > bin2) {
            sc[u] = NEGMAX;
        } else {
            float a = 0.0f;
            const float* kp = &g_k[j * 128 + h * DK];
            #pragma unroll
            for (int d = 0; d < DK; d++) a += qv[d] * kp[d];
            sc[u] = a * scaling;
        }
    }
    float mx = fmaxf(sc[0], sc[1]);
    #pragma unroll
    for (int o = 16; o; o >>= 1) mx = fmaxf(mx, __shfl_xor_sync(0xffffffffu, mx, o));
    if ((t & 31) == 0) red[t >> 5] = mx;
    __syncthreads();
    mx = red[0];
    #pragma unroll
    for (int w = 1; w < 8; w++) mx = fmaxf(mx, red[w]);

    float e0 = expf(sc[0] - mx);
    float e1 = expf(sc[1] - mx);
    float ss = e0 + e1;
    #pragma unroll
    for (int o = 16; o; o >>= 1) ss += __shfl_xor_sync(0xffffffffu, ss, o);
    __syncthreads();
    if ((t & 31) == 0) red[t >> 5] = ss;
    __syncthreads();
    ss = red[0];
    #pragma unroll
    for (int w = 1; w < 8; w++) ss += red[w];
    float inv = 1.0f / ss;

    int iblk = i >> 7, ib = i & 127;
    size_t blkbase = ((size_t)(h * 4 + iblk) * 16) * 4096;
    float vals[2] = {e0 * inv, e1 * inv};
    #pragma unroll
    for (int u = 0; u < 2; u++) {
        int j = t + u * 256;
        int kc = j >> 5;
        g_attn[blkbase + (size_t)kc * 4096 + afrag_addr(ib, j & 31, 4)] = vals[u];
    }
}

// =====================================================================
// K3 (mma tf32): v = LN(msa)@Wv + bv -> g_vT B-fragment-permuted.
// 64-row tiles, M=64 N=64 K=64 per tile. grid=1024, block=256.
// =====================================================================
__global__ void __launch_bounds__(256) v_mma_kernel(
        const float* __restrict__ msa,
        const float* __restrict__ n1g, const float* __restrict__ n1b,
        const float* __restrict__ Wv, const float* __restrict__ bv) {
    __shared__ float Wvp[4096];
    __shared__ float Ap[4096];
    __shared__ float sbv[DM], sg[DM], sb[DM];
    int t = threadIdx.x, warp = t >> 5, lane = t & 31;
    int rg = lane >> 2, q2 = (lane & 3) * 2;

    for (int i = t; i < 4096; i += 256) {
        int c = i >> 6, n = i & 63;
        Wvp[bfrag_addr(c, n, 8)] = Wv[i];
    }
    if (t < DM) { sbv[t] = bv[t]; sg[t] = n1g[t]; sb[t] = n1b[t]; }
    __syncthreads();

    int wm = warp >> 2, wn = warp & 3;
    for (int tile = blockIdx.x; tile < NROWS / 64; tile += gridDim.x) {
        size_t row0 = (size_t)tile * 64;
        // ---- LN1 -> Ap ----
        #pragma unroll
        for (int rr = 0; rr < 8; rr++) {
            int row = warp * 8 + rr;
            float2 x2 = *(const float2*)&msa[(row0 + row) * DM + 2 * lane];
            float sum = x2.x + x2.y;
            #pragma unroll
            for (int o = 16; o; o >>= 1) sum += __shfl_xor_sync(0xffffffffu, sum, o);
            float m = sum * (1.0f / DM);
            float d0 = x2.x - m, d1 = x2.y - m;
            float vv = d0 * d0 + d1 * d1;
            #pragma unroll
            for (int o = 16; o; o >>= 1) vv += __shfl_xor_sync(0xffffffffu, vv, o);
            float r = rsqrtf(vv * (1.0f / DM) + EPSLN);
            int c0 = 2 * lane;
            Ap[afrag_addr(row, c0, 8)]     = d0 * r * sg[c0]     + sb[c0];
            Ap[afrag_addr(row, c0 + 1, 8)] = d1 * r * sg[c0 + 1] + sb[c0 + 1];
        }
        __syncthreads();
        // ---- GEMM 64x64x64: warp = 2mt x 2nt x 8ks ----
        float acc[2][2][4];
        #pragma unroll
        for (int x = 0; x < 2; x++)
            #pragma unroll
            for (int y = 0; y < 2; y++)
                #pragma unroll
                for (int r = 0; r < 4; r++) acc[x][y][r] = 0.0f;
        #pragma unroll
        for (int ks = 0; ks < 8; ks++) {
            float4 af[2];
            float2 bf[2];
            #pragma unroll
            for (int mt = 0; mt < 2; mt++)
                af[mt] = *(const float4*)&Ap[((wm * 2 + mt) * 8 + ks) * 128 + lane * 4];
            #pragma unroll
            for (int nt = 0; nt < 2; nt++)
                bf[nt] = *(const float2*)&Wvp[((wn * 2 + nt) * 8 + ks) * 64 + lane * 2];
            #pragma unroll
            for (int mt = 0; mt < 2; mt++)
                #pragma unroll
                for (int nt = 0; nt < 2; nt++)
                    mma_tf32(acc[mt][nt][0], acc[mt][nt][1], acc[mt][nt][2], acc[mt][nt][3],
                             F2U(af[mt].x), F2U(af[mt].y), F2U(af[mt].z), F2U(af[mt].w),
                             F2U(bf[nt].x), F2U(bf[nt].y));
        }
        // ---- epilogue: +bv, scatter to g_vT B-frag layout ----
        int n = (int)(row0 >> 9);
        int j0 = (int)(row0 & 511);
        int blk = n >> 3;
        #pragma unroll
        for (int mt = 0; mt < 2; mt++) {
            #pragma unroll
            for (int nt = 0; nt < 2; nt++) {
                int rt0 = wm * 32 + mt * 16 + rg;
                int c0 = wn * 16 + nt * 8 + q2;
                #pragma unroll
                for (int e = 0; e < 4; e++) {
                    int rt = rt0 + (e >> 1) * 8;
                    int cc = c0 + (e & 1);
                    float val = acc[mt][nt][e] + sbv[cc];
                    int h = cc >> 4, d = cc & 15;
                    int j = j0 + rt, kc = j >> 5, kr = j & 31;
                    int nb = (n & 7) * 16 + d;
                    g_vT[((size_t)(h * 32 + blk) * 16 + kc) * 4096
                         + bfrag_addr(kr, nb, 4)] = val;
                }
            }
        }
        __syncthreads();
    }
}

// =====================================================================
// K4 (mma tf32): per-head C(512x4096) = attn @ vT; both inputs arrive
// pre-permuted -> pure float4 fills. Epilogue -> g_attout A-frag tiles.
// grid=(32,4,4), block=256.
// =====================================================================
__global__ void __launch_bounds__(256, 2) gemm_attn_mma() {
    int h  = blockIdx.z;
    const float* __restrict__ Abase =
        g_attn + ((size_t)(h * 4 + blockIdx.y) * 16) * 4096;
    const float* __restrict__ Bbase =
        g_vT + ((size_t)(h * 32 + blockIdx.x) * 16) * 4096;
    int n0 = blockIdx.x * 128;
    int i0 = blockIdx.y * 128;

    __shared__ float sA[4096];
    __shared__ float sB[4096];

    int t = threadIdx.x, wid = t >> 5, lid = t & 31;
    int wm = wid >> 2, wn = wid & 3;

    float acc[4][4][4];
    #pragma unroll
    for (int x = 0; x < 4; x++)
        #pragma unroll
        for (int y = 0; y < 4; y++)
            #pragma unroll
            for (int r = 0; r < 4; r++) acc[x][y][r] = 0.0f;

    for (int kc = 0; kc < 16; kc++) {
        const float4* srcA = (const float4*)(Abase + (size_t)kc * 4096);
        const float4* srcB = (const float4*)(Bbase + (size_t)kc * 4096);
        #pragma unroll
        for (int u = 0; u < 4; u++) {
            int id = t + u * 256;
            *(float4*)&sA[id * 4] = srcA[id];
            *(float4*)&sB[id * 4] = srcB[id];
        }
        __syncthreads();
        #pragma unroll
        for (int ks = 0; ks < 4; ks++) {
            uint32_t bf[4][2];
            #pragma unroll
            for (int nt2 = 0; nt2 < 4; nt2++) {
                int nt = wn * 4 + nt2;
                float2 b2 = *(const float2*)&sB[(nt * 4 + ks) * 64 + lid * 2];
                bf[nt2][0] = F2U(b2.x);
                bf[nt2][1] = F2U(b2.y);
            }
            #pragma unroll
            for (int mt2 = 0; mt2 < 4; mt2++) {
                int mt = wm * 4 + mt2;
                float4 a4 = *(const float4*)&sA[(mt * 4 + ks) * 128 + lid * 4];
                #pragma unroll
                for (int nt2 = 0; nt2 < 4; nt2++)
                    mma_tf32(acc[mt2][nt2][0], acc[mt2][nt2][1],
                             acc[mt2][nt2][2], acc[mt2][nt2][3],
                             F2U(a4.x), F2U(a4.y), F2U(a4.z), F2U(a4.w),
                             bf[nt2][0], bf[nt2][1]);
            }
        }
        __syncthreads();
    }

    // epilogue -> g_attout A-frag-permuted 64-row tiles
    int rg = lid >> 2, q2 = (lid & 3) * 2;
    #pragma unroll
    for (int mt2 = 0; mt2 < 4; mt2++) {
        int rowA = i0 + wm * 64 + mt2 * 16 + rg;
        int rt = rowA & 63;
        #pragma unroll
        for (int nt2 = 0; nt2 < 4; nt2++) {
            int col = n0 + wn * 32 + nt2 * 8 + q2;
            int n = col >> 4, d = col & 15;
            int c = h * DV + d;
            size_t r = (size_t)n * L + rowA;
            float* p = g_attout + (r >> 6) * 4096;
            int base = afrag_addr(rt, c, 8);
            p[base]     = acc[mt2][nt2][0];
            p[base + 4] = acc[mt2][nt2][1];
            p[base + 1] = acc[mt2][nt2][2];
            p[base + 5] = acc[mt2][nt2][3];
        }
    }
}

// =====================================================================
// K5 (mma tf32): msax = msa + attout@Wo + bo.  A pre-permuted in gmem.
// grid=1024, block=256.
// =====================================================================
__global__ void __launch_bounds__(256) oproj_mma_kernel(
        const float* __restrict__ msa,
        const float* __restrict__ Wo, const float* __restrict__ bo) {
    __shared__ float Wop[4096];
    __shared__ float Ap[4096];
    __shared__ float sbo[DM];
    int t = threadIdx.x, warp = t >> 5, lane = t & 31;
    int rg = lane >> 2, q2 = (lane & 3) * 2;

    for (int i = t; i < 4096; i += 256) {
        int c = i >> 6, n = i & 63;
        Wop[bfrag_addr(c, n, 8)] = Wo[i];
    }
    if (t < DM) sbo[t] = bo[t];
    __syncthreads();

    int wm = warp >> 2, wn = warp & 3;
    for (int tile = blockIdx.x; tile < NROWS / 64; tile += gridDim.x) {
        size_t row0 = (size_t)tile * 64;
        const float4* src = (const float4*)(g_attout + (size_t)tile * 4096);
        #pragma unroll
        for (int u = 0; u < 4; u++) {
            int id = t + u * 256;
            *(float4*)&Ap[id * 4] = src[id];
        }
        __syncthreads();
        float acc[2][2][4];
        #pragma unroll
        for (int x = 0; x < 2; x++)
            #pragma unroll
            for (int y = 0; y < 2; y++)
                #pragma unroll
                for (int r = 0; r < 4; r++) acc[x][y][r] = 0.0f;
        #pragma unroll
        for (int ks = 0; ks < 8; ks++) {
            float4 af[2];
            float2 bf[2];
            #pragma unroll
            for (int mt = 0; mt < 2; mt++)
                af[mt] = *(const float4*)&Ap[((wm * 2 + mt) * 8 + ks) * 128 + lane * 4];
            #pragma unroll
            for (int nt = 0; nt < 2; nt++)
                bf[nt] = *(const float2*)&Wop[((wn * 2 + nt) * 8 + ks) * 64 + lane * 2];
            #pragma unroll
            for (int mt = 0; mt < 2; mt++)
                #pragma unroll
                for (int nt = 0; nt < 2; nt++)
                    mma_tf32(acc[mt][nt][0], acc[mt][nt][1], acc[mt][nt][2], acc[mt][nt][3],
                             F2U(af[mt].x), F2U(af[mt].y), F2U(af[mt].z), F2U(af[mt].w),
                             F2U(bf[nt].x), F2U(bf[nt].y));
        }
        // epilogue: + bo + msa residual -> g_msax (raw layout)
        #pragma unroll
        for (int mt = 0; mt < 2; mt++) {
            #pragma unroll
            for (int nt = 0; nt < 2; nt++) {
                int rt0 = wm * 32 + mt * 16 + rg;
                int c0 = wn * 16 + nt * 8 + q2;
                float bo0 = sbo[c0], bo1 = sbo[c0 + 1];
                #pragma unroll
                for (int half = 0; half < 2; half++) {
                    size_t r = row0 + rt0 + half * 8;
                    float2 m2 = *(const float2*)&msa[r * DM + c0];
                    float2 y = make_float2(acc[mt][nt][half * 2]     + bo0 + m2.x,
                                           acc[mt][nt][half * 2 + 1] + bo1 + m2.y);
                    *(float2*)&g_msax[r * DM + c0] = y;
                }
            }
        }
        __syncthreads();
    }
}

// =====================================================================
// K6 (mma tf32): fused FF + final LN (validated R5).
// =====================================================================
struct FFS3 {
    float W1p[DM * FFH];
    float W2p[FFH * DM];
    float b1s[FFH];
    float b2s[DM], g2[DM], bn2[DM], g3[DM], bn3[DM];
    float Xs[64 * DM];
    float Ap[64 * DM];
    float Hp[64 * FFH];
};
extern __shared__ unsigned char ff_raw[];

__global__ void __launch_bounds__(256) ff_mma_kernel(
        const float* __restrict__ n2g, const float* __restrict__ n2b,
        const float* __restrict__ W1, const float* __restrict__ b1,
        const float* __restrict__ W2, const float* __restrict__ b2,
        const float* __restrict__ n3g, const float* __restrict__ n3b,
        float* __restrict__ out) {
    FFS3* s = (FFS3*)ff_raw;
    int t = threadIdx.x, warp = t >> 5, lane = t & 31;
    int rg = lane >> 2, q2 = (lane & 3) * 2;

    for (int i = t; i < DM * FFH; i += 256) {
        int c = i >> 8, n = i & 255;
        s->W1p[bfrag_addr(c, n, 8)] = W1[i];
    }
    for (int i = t; i < FFH * DM; i += 256) {
        int c = i >> 6, n = i & 63;
        s->W2p[bfrag_addr(c, n, 32)] = W2[i];
    }
    s->b1s[t] = b1[t];
    if (t < DM) { s->b2s[t] = b2[t]; s->g2[t] = n2g[t]; s->bn2[t] = n2b[t];
                  s->g3[t] = n3g[t]; s->bn3[t] = n3b[t]; }
    __syncthreads();

    const int nTiles = NROWS / 64;
    for (int tile = blockIdx.x; tile < nTiles; tile += gridDim.x) {
        size_t row0 = (size_t)tile * 64;
        #pragma unroll
        for (int i = 0; i < 4; i++) {
            int f4 = t * 4 + i;
            *(float4*)&s->Xs[f4 * 4] = *(const float4*)&g_msax[row0 * DM + f4 * 4];
        }
        __syncthreads();
        #pragma unroll
        for (int rr = 0; rr < 8; rr++) {
            int row = warp * 8 + rr;
            float2 x2 = *(const float2*)&s->Xs[row * DM + 2 * lane];
            float sum = x2.x + x2.y;
            #pragma unroll
            for (int o = 16; o; o >>= 1) sum += __shfl_xor_sync(0xffffffffu, sum, o);
            float m = sum * (1.0f / DM);
            float d0 = x2.x - m, d1 = x2.y - m;
            float vv = d0 * d0 + d1 * d1;
            #pragma unroll
            for (int o = 16; o; o >>= 1) vv += __shfl_xor_sync(0xffffffffu, vv, o);
            float r = rsqrtf(vv * (1.0f / DM) + EPSLN);
            int c0 = 2 * lane;
            s->Ap[afrag_addr(row, c0, 8)]     = d0 * r * s->g2[c0]     + s->bn2[c0];
            s->Ap[afrag_addr(row, c0 + 1, 8)] = d1 * r * s->g2[c0 + 1] + s->bn2[c0 + 1];
        }
        __syncthreads();
        {
            int wm = warp >> 2, wn = warp & 3;
            float acc1[2][8][4];
            #pragma unroll
            for (int x = 0; x < 2; x++)
                #pragma unroll
                for (int y = 0; y < 8; y++)
                    #pragma unroll
                    for (int r = 0; r < 4; r++) acc1[x][y][r] = 0.0f;
            #pragma unroll
            for (int ks = 0; ks < 8; ks++) {
                float4 af0 = *(const float4*)&s->Ap[((wm * 2 + 0) * 8 + ks) * 128 + lane * 4];
                float4 af1 = *(const float4*)&s->Ap[((wm * 2 + 1) * 8 + ks) * 128 + lane * 4];
                #pragma unroll
                for (int nt = 0; nt < 8; nt++) {
                    float2 b2v = *(const float2*)&s->W1p[((wn * 8 + nt) * 8 + ks) * 64 + lane * 2];
                    mma_tf32(acc1[0][nt][0], acc1[0][nt][1], acc1[0][nt][2], acc1[0][nt][3],
                             F2U(af0.x), F2U(af0.y), F2U(af0.z), F2U(af0.w),
                             F2U(b2v.x), F2U(b2v.y));
                    mma_tf32(acc1[1][nt][0], acc1[1][nt][1], acc1[1][nt][2], acc1[1][nt][3],
                             F2U(af1.x), F2U(af1.y), F2U(af1.z), F2U(af1.w),
                             F2U(b2v.x), F2U(b2v.y));
                }
            }
            #pragma unroll
            for (int mt = 0; mt < 2; mt++) {
                int mt2 = wm * 2 + mt;
                #pragma unroll
                for (int nt = 0; nt < 8; nt++) {
                    int ks2 = wn * 8 + nt;
                    int c0 = ks2 * 8 + q2;
                    float b1a = s->b1s[c0], b1b = s->b1s[c0 + 1];
                    float v0 = fmaxf(acc1[mt][nt][0] + b1a, 0.f);
                    float v1 = fmaxf(acc1[mt][nt][1] + b1b, 0.f);
                    float v2 = fmaxf(acc1[mt][nt][2] + b1a, 0.f);
                    float v3 = fmaxf(acc1[mt][nt][3] + b1b, 0.f);
                    int fb = (mt2 * 32 + ks2) * 128 + rg * 16;
                    int a0 = fb + (q2 & 3) * 4 + ((q2 >> 2) << 1);
                    int kk1 = q2 + 1;
                    int a1 = fb + (kk1 & 3) * 4 + ((kk1 >> 2) << 1);
                    *(float2*)&s->Hp[a0] = make_float2(v0, v2);
                    *(float2*)&s->Hp[a1] = make_float2(v1, v3);
                }
            }
        }
        __syncthreads();
        {
            int kg = warp >> 2, wm2 = (warp >> 1) & 1, wn2 = warp & 1;
            float acc2[2][4][4];
            #pragma unroll
            for (int x = 0; x < 2; x++)
                #pragma unroll
                for (int y = 0; y < 4; y++)
                    #pragma unroll
                    for (int r = 0; r < 4; r++) acc2[x][y][r] = 0.0f;
            #pragma unroll 8
            for (int ks = 0; ks < 16; ks++) {
                int ksg = kg * 16 + ks;
                float4 af0 = *(const float4*)&s->Hp[((wm2 * 2 + 0) * 32 + ksg) * 128 + lane * 4];
                float4 af1 = *(const float4*)&s->Hp[((wm2 * 2 + 1) * 32 + ksg) * 128 + lane * 4];
                #pragma unroll
                for (int nt = 0; nt < 4; nt++) {
                    float2 b2v = *(const float2*)&s->W2p[((wn2 * 4 + nt) * 32 + ksg) * 64 + lane * 2];
                    mma_tf32(acc2[0][nt][0], acc2[0][nt][1], acc2[0][nt][2], acc2[0][nt][3],
                             F2U(af0.x), F2U(af0.y), F2U(af0.z), F2U(af0.w),
                             F2U(b2v.x), F2U(b2v.y));
                    mma_tf32(acc2[1][nt][0], acc2[1][nt][1], acc2[1][nt][2], acc2[1][nt][3],
                             F2U(af1.x), F2U(af1.y), F2U(af1.z), F2U(af1.w),
                             F2U(b2v.x), F2U(b2v.y));
                }
            }
            __syncthreads();
            float* Ps = s->Hp;
            #pragma unroll
            for (int mt = 0; mt < 2; mt++)
                #pragma unroll
                for (int nt = 0; nt < 4; nt++) {
                    int r0 = wm2 * 32 + mt * 16 + rg;
                    int c0 = wn2 * 32 + nt * 8 + q2;
                    *(float2*)&Ps[kg * 4608 + r0 * 72 + c0] =
                        make_float2(acc2[mt][nt][0], acc2[mt][nt][1]);
                    *(float2*)&Ps[kg * 4608 + (r0 + 8) * 72 + c0] =
                        make_float2(acc2[mt][nt][2], acc2[mt][nt][3]);
                }
        }
        __syncthreads();
        {
            float* Ps = s->Hp;
            #pragma unroll
            for (int rr = 0; rr < 8; rr++) {
                int row = warp * 8 + rr;
                float2 x2 = *(const float2*)&s->Xs[row * DM + 2 * lane];
                float2 p0 = *(const float2*)&Ps[row * 72 + 2 * lane];
                float2 p1 = *(const float2*)&Ps[4608 + row * 72 + 2 * lane];
                float y0 = x2.x + s->b2s[2 * lane]     + p0.x + p1.x;
                float y1 = x2.y + s->b2s[2 * lane + 1] + p0.y + p1.y;
                float sum = y0 + y1;
                #pragma unroll
                for (int o = 16; o; o >>= 1) sum += __shfl_xor_sync(0xffffffffu, sum, o);
                float m = sum * (1.0f / DM);
                float d0 = y0 - m, d1 = y1 - m;
                float vv = d0 * d0 + d1 * d1;
                #pragma unroll
                for (int o = 16; o; o >>= 1) vv += __shfl_xor_sync(0xffffffffu, vv, o);
                float r = rsqrtf(vv * (1.0f / DM) + EPSLN);
                size_t ob = (row0 + row) * DM;
                out[ob + 2 * lane]     = d0 * r * s->g3[2 * lane]     + s->bn3[2 * lane];
                out[ob + 2 * lane + 1] = d1 * r * s->g3[2 * lane + 1] + s->bn3[2 * lane + 1];
            }
        }
        __syncthreads();
    }
}

// =====================================================================
extern "C" void kernel_launch(void* const* d_in, const int* in_sizes, int n_in,
                              void* d_out, int out_size) {
    const float* msa   = (const float*)d_in[0];
    const float* Ca    = (const float*)d_in[1];
    const float* state = (const float*)d_in[2];
    const float* ns_g  = (const float*)d_in[3];
    const float* ns_b  = (const float*)d_in[4];
    const float* n1_g  = (const float*)d_in[5];
    const float* n1_b  = (const float*)d_in[6];
    const float* Wq    = (const float*)d_in[7];
    const float* bq    = (const float*)d_in[8];
    const float* Wk    = (const float*)d_in[9];
    const float* bk    = (const float*)d_in[10];
    const float* Wv    = (const float*)d_in[11];
    const float* bv    = (const float*)d_in[12];
    const float* Wo    = (const float*)d_in[13];
    const float* bo    = (const float*)d_in[14];
    const float* n2_g  = (const float*)d_in[15];
    const float* n2_b  = (const float*)d_in[16];
    const float* W1    = (const float*)d_in[17];
    const float* b1    = (const float*)d_in[18];
    const float* W2    = (const float*)d_in[19];
    const float* b2    = (const float*)d_in[20];
    const float* n3_g  = (const float*)d_in[21];
    const float* n3_b  = (const float*)d_in[22];
    float* out = (float*)d_out;

    cudaFuncSetAttribute(ff_mma_kernel, cudaFuncAttributeMaxDynamicSharedMemorySize,
                         (int)sizeof(FFS3));

    qk_kernel<<<L, 128>>>(state, ns_g, ns_b, Wq, bq, Wk, bk);
    attn_kernel<<<dim3(L, NH), 256>>>(Ca);
    v_mma_kernel<<<1024, 256>>>(msa, n1_g, n1_b, Wv, bv);
    gemm_attn_mma<<<dim3(32, 4, 4), 256>>>();
    oproj_mma_kernel<<<1024, 256>>>(msa, Wo, bo);
    ff_mma_kernel<<<148, 256, sizeof(FFS3)>>>(n2_g, n2_b, W1, b1, W2, b2, n3_g, n3_b, out);
}

// round 7
// speedup vs baseline: 4.1877x; 1.0431x over previous
#include <cuda_runtime.h>
#include <cuda_bf16.h>
#include <math.h>
#include <stdint.h>

// ---------------- problem constants ----------------
#define L 512
#define NSEQ 256
#define DM 64          // D_MSA
#define DS 32          // D_STATE
#define NH 4           // heads
#define DK 32
#define DV 16
#define FFH 256        // D_MSA * R_FF
#define NROWS (NSEQ * L)   // 131072
#define EPSLN 1e-5f
#define NEGMAX (-3.402823466e38f)

// ---------------- scratch (device globals: no runtime allocs) ----------------
__device__ float g_q[L * NH * DK];            // (l, h*32+d)
__device__ float g_k[L * NH * DK];
// g_attn: A-fragment-permuted: [h][iblk(4)][kc(16)][4096]
__device__ float g_attn[NH * L * L];
// g_vT: B-fragment-permuted: [h][nblk(32)][kc(16)][4096]
__device__ float g_vT[NH * L * NSEQ * DV];
// g_attout: A-fragment-permuted 64-row tiles: [tile(2048)][4096]
__device__ float g_attout[NROWS * DM];
__device__ float g_msax[NROWS * DM];          // msa + attn_out (raw rows)

// ---------------- mma.sync tf32 helper (valid on plain sm_100) -------
__device__ __forceinline__ void mma_tf32(float& c0, float& c1, float& c2, float& c3,
                                         uint32_t a0, uint32_t a1, uint32_t a2, uint32_t a3,
                                         uint32_t b0, uint32_t b1) {
    asm volatile(
        "mma.sync.aligned.m16n8k8.row.col.f32.tf32.tf32.f32 "
        "{%0,%1,%2,%3}, {%4,%5,%6,%7}, {%8,%9}, {%0,%1,%2,%3};"
        : "+f"(c0), "+f"(c1), "+f"(c2), "+f"(c3)
        : "r"(a0), "r"(a1), "r"(a2), "r"(a3), "r"(b0), "r"(b1));
}
#define F2U(x) __float_as_uint(x)

__device__ __forceinline__ uint32_t smem_u32(const void* p) {
    uint32_t a;
    asm("{ .reg .u64 tmp; cvta.to.shared.u64 tmp, %1; cvt.u32.u64 %0, tmp; }"
        : "=r"(a) : "l"(p));
    return a;
}
__device__ __forceinline__ void cp16(uint32_t smem, const void* gmem) {
    asm volatile("cp.async.cg.shared.global [%0], [%1], 16;" :: "r"(smem), "l"(gmem));
}
#define CP_COMMIT() asm volatile("cp.async.commit_group;")
#define CP_WAIT2()  asm volatile("cp.async.wait_group 2;")

// fragment address helpers (KS8 = K/8 of the tile)
__device__ __forceinline__ int afrag_addr(int r, int c, int KS8) {
    return ((r >> 4) * KS8 + (c >> 3)) * 128 + (r & 7) * 16 + ((r >> 3) & 1)
         + (c & 3) * 4 + ((c >> 2) & 1) * 2;
}
__device__ __forceinline__ int bfrag_addr(int c, int n, int KS8) {
    return ((n >> 3) * KS8 + (c >> 3)) * 64 + (n & 7) * 8 + (c & 3) * 2 + ((c >> 2) & 1);
}

// =====================================================================
// K1: st = LN(state); q = st@Wq+bq; k = st@Wk+bk.  grid=512, block=128
// =====================================================================
__global__ void qk_kernel(const float* __restrict__ state,
                          const float* __restrict__ nsg, const float* __restrict__ nsb,
                          const float* __restrict__ Wq, const float* __restrict__ bq,
                          const float* __restrict__ Wk, const float* __restrict__ bk) {
    int l = blockIdx.x;
    int t = threadIdx.x;                // 0..127
    __shared__ float st[DS];
    if (t < DS) {
        float x = state[l * DS + t];
        float s = x;
        #pragma unroll
        for (int o = 16; o; o >>= 1) s += __shfl_xor_sync(0xffffffffu, s, o);
        float m = s * (1.0f / DS);
        float d = x - m;
        float v = d * d;
        #pragma unroll
        for (int o = 16; o; o >>= 1) v += __shfl_xor_sync(0xffffffffu, v, o);
        float r = rsqrtf(v * (1.0f / DS) + EPSLN);
        st[t] = d * r * nsg[t] + nsb[t];
    }
    __syncthreads();
    float aq = bq[t], ak = bk[t];
    #pragma unroll
    for (int c = 0; c < DS; c++) {
        float s = st[c];
        aq += s * Wq[c * 128 + t];
        ak += s * Wk[c * 128 + t];
    }
    g_q[l * 128 + t] = aq;
    g_k[l * 128 + t] = ak;
}

// =====================================================================
// K2: attn softmax -> A-fragment-permuted gmem (validated layout)
// =====================================================================
__global__ void attn_kernel(const float* __restrict__ Ca) {
    int i = blockIdx.x, h = blockIdx.y;
    int t = threadIdx.x;
    __shared__ float qv[DK];
    __shared__ float red[8];
    __shared__ float cai[3];
    if (t < DK) qv[t] = g_q[i * 128 + h * DK + t];
    if (t < 3)  cai[t] = Ca[i * 3 + t];
    __syncthreads();

    float bin = (float)(4 * (h + 1)) / 10.0f;
    float bin2 = bin * bin;
    const float scaling = 0.17677669529663687f;  // 1/sqrt(32)
    float cx = cai[0], cy = cai[1], cz = cai[2];

    float sc[2];
    #pragma unroll
    for (int u = 0; u < 2; u++) {
        int j = t + u * 256;
        float dx = Ca[3 * j] - cx, dy = Ca[3 * j + 1] - cy, dz = Ca[3 * j + 2] - cz;
        float sq = fmaxf(dx * dx + dy * dy + dz * dz, 1e-12f);
        if (sq > bin2) {
            sc[u] = NEGMAX;
        } else {
            float a = 0.0f;
            const float* kp = &g_k[j * 128 + h * DK];
            #pragma unroll
            for (int d = 0; d < DK; d++) a += qv[d] * kp[d];
            sc[u] = a * scaling;
        }
    }
    float mx = fmaxf(sc[0], sc[1]);
    #pragma unroll
    for (int o = 16; o; o >>= 1) mx = fmaxf(mx, __shfl_xor_sync(0xffffffffu, mx, o));
    if ((t & 31) == 0) red[t >> 5] = mx;
    __syncthreads();
    mx = red[0];
    #pragma unroll
    for (int w = 1; w < 8; w++) mx = fmaxf(mx, red[w]);

    float e0 = expf(sc[0] - mx);
    float e1 = expf(sc[1] - mx);
    float ss = e0 + e1;
    #pragma unroll
    for (int o = 16; o; o >>= 1) ss += __shfl_xor_sync(0xffffffffu, ss, o);
    __syncthreads();
    if ((t & 31) == 0) red[t >> 5] = ss;
    __syncthreads();
    ss = red[0];
    #pragma unroll
    for (int w = 1; w < 8; w++) ss += red[w];
    float inv = 1.0f / ss;

    int iblk = i >> 7, ib = i & 127;
    size_t blkbase = ((size_t)(h * 4 + iblk) * 16) * 4096;
    float vals[2] = {e0 * inv, e1 * inv};
    #pragma unroll
    for (int u = 0; u < 2; u++) {
        int j = t + u * 256;
        int kc = j >> 5;
        g_attn[blkbase + (size_t)kc * 4096 + afrag_addr(ib, j & 31, 4)] = vals[u];
    }
}

// =====================================================================
// K3 (mma tf32): v = LN(msa)@Wv + bv -> g_vT B-fragment-permuted.
// =====================================================================
__global__ void __launch_bounds__(256) v_mma_kernel(
        const float* __restrict__ msa,
        const float* __restrict__ n1g, const float* __restrict__ n1b,
        const float* __restrict__ Wv, const float* __restrict__ bv) {
    __shared__ float Wvp[4096];
    __shared__ float Ap[4096];
    __shared__ float sbv[DM], sg[DM], sb[DM];
    int t = threadIdx.x, warp = t >> 5, lane = t & 31;
    int rg = lane >> 2, q2 = (lane & 3) * 2;

    for (int i = t; i < 4096; i += 256) {
        int c = i >> 6, n = i & 63;
        Wvp[bfrag_addr(c, n, 8)] = Wv[i];
    }
    if (t < DM) { sbv[t] = bv[t]; sg[t] = n1g[t]; sb[t] = n1b[t]; }
    __syncthreads();

    int wm = warp >> 2, wn = warp & 3;
    for (int tile = blockIdx.x; tile < NROWS / 64; tile += gridDim.x) {
        size_t row0 = (size_t)tile * 64;
        #pragma unroll
        for (int rr = 0; rr < 8; rr++) {
            int row = warp * 8 + rr;
            float2 x2 = *(const float2*)&msa[(row0 + row) * DM + 2 * lane];
            float sum = x2.x + x2.y;
            #pragma unroll
            for (int o = 16; o; o >>= 1) sum += __shfl_xor_sync(0xffffffffu, sum, o);
            float m = sum * (1.0f / DM);
            float d0 = x2.x - m, d1 = x2.y - m;
            float vv = d0 * d0 + d1 * d1;
            #pragma unroll
            for (int o = 16; o; o >>= 1) vv += __shfl_xor_sync(0xffffffffu, vv, o);
            float r = rsqrtf(vv * (1.0f / DM) + EPSLN);
            int c0 = 2 * lane;
            Ap[afrag_addr(row, c0, 8)]     = d0 * r * sg[c0]     + sb[c0];
            Ap[afrag_addr(row, c0 + 1, 8)] = d1 * r * sg[c0 + 1] + sb[c0 + 1];
        }
        __syncthreads();
        float acc[2][2][4];
        #pragma unroll
        for (int x = 0; x < 2; x++)
            #pragma unroll
            for (int y = 0; y < 2; y++)
                #pragma unroll
                for (int r = 0; r < 4; r++) acc[x][y][r] = 0.0f;
        #pragma unroll
        for (int ks = 0; ks < 8; ks++) {
            float4 af[2];
            float2 bf[2];
            #pragma unroll
            for (int mt = 0; mt < 2; mt++)
                af[mt] = *(const float4*)&Ap[((wm * 2 + mt) * 8 + ks) * 128 + lane * 4];
            #pragma unroll
            for (int nt = 0; nt < 2; nt++)
                bf[nt] = *(const float2*)&Wvp[((wn * 2 + nt) * 8 + ks) * 64 + lane * 2];
            #pragma unroll
            for (int mt = 0; mt < 2; mt++)
                #pragma unroll
                for (int nt = 0; nt < 2; nt++)
                    mma_tf32(acc[mt][nt][0], acc[mt][nt][1], acc[mt][nt][2], acc[mt][nt][3],
                             F2U(af[mt].x), F2U(af[mt].y), F2U(af[mt].z), F2U(af[mt].w),
                             F2U(bf[nt].x), F2U(bf[nt].y));
        }
        int n = (int)(row0 >> 9);
        int j0 = (int)(row0 & 511);
        int blk = n >> 3;
        #pragma unroll
        for (int mt = 0; mt < 2; mt++) {
            #pragma unroll
            for (int nt = 0; nt < 2; nt++) {
                int rt0 = wm * 32 + mt * 16 + rg;
                int c0 = wn * 16 + nt * 8 + q2;
                #pragma unroll
                for (int e = 0; e < 4; e++) {
                    int rt = rt0 + (e >> 1) * 8;
                    int cc = c0 + (e & 1);
                    float val = acc[mt][nt][e] + sbv[cc];
                    int h = cc >> 4, d = cc & 15;
                    int j = j0 + rt, kc = j >> 5, kr = j & 31;
                    int nb = (n & 7) * 16 + d;
                    g_vT[((size_t)(h * 32 + blk) * 16 + kc) * 4096
                         + bfrag_addr(kr, nb, 4)] = val;
                }
            }
        }
        __syncthreads();
    }
}

// =====================================================================
// K4 (mma tf32 + cp.async 3-stage): per-head C = attn @ vT.
// Both inputs pre-permuted -> pure 16B async copies. grid=(32,4,4).
// dyn smem: sA[3][4096] + sB[3][4096] = 96 KB.
// =====================================================================
extern __shared__ float gsh[];
__global__ void __launch_bounds__(256, 2) gemm_attn_mma() {
    int h  = blockIdx.z;
    const float* __restrict__ Abase =
        g_attn + ((size_t)(h * 4 + blockIdx.y) * 16) * 4096;
    const float* __restrict__ Bbase =
        g_vT + ((size_t)(h * 32 + blockIdx.x) * 16) * 4096;
    int n0 = blockIdx.x * 128;
    int i0 = blockIdx.y * 128;

    float* sA = gsh;              // 3 * 4096
    float* sB = gsh + 12288;      // 3 * 4096

    int t = threadIdx.x, wid = t >> 5, lid = t & 31;
    int wm = wid >> 2, wn = wid & 3;
    uint32_t aAddr = smem_u32(sA) + t * 16;
    uint32_t bAddr = smem_u32(sB) + t * 16;

    float acc[4][4][4];
    #pragma unroll
    for (int x = 0; x < 4; x++)
        #pragma unroll
        for (int y = 0; y < 4; y++)
            #pragma unroll
            for (int r = 0; r < 4; r++) acc[x][y][r] = 0.0f;

    // 3-stage cp.async pipeline
    #pragma unroll 1
    for (int p = 0; p < 2; p++) {
        int st = p;
        const float4* srcA = (const float4*)(Abase + (size_t)p * 4096) + t;
        const float4* srcB = (const float4*)(Bbase + (size_t)p * 4096) + t;
        #pragma unroll
        for (int u = 0; u < 4; u++) {
            cp16(aAddr + st * 16384 + u * 4096, srcA + u * 256);
            cp16(bAddr + st * 16384 + u * 4096, srcB + u * 256);
        }
        CP_COMMIT();
    }

    #pragma unroll 1
    for (int kc = 0; kc < 16; kc++) {
        if (kc + 2 < 16) {
            int st = (kc + 2) % 3;
            const float4* srcA = (const float4*)(Abase + (size_t)(kc + 2) * 4096) + t;
            const float4* srcB = (const float4*)(Bbase + (size_t)(kc + 2) * 4096) + t;
            #pragma unroll
            for (int u = 0; u < 4; u++) {
                cp16(aAddr + st * 16384 + u * 4096, srcA + u * 256);
                cp16(bAddr + st * 16384 + u * 4096, srcB + u * 256);
            }
        }
        CP_COMMIT();
        CP_WAIT2();
        __syncthreads();
        const float* cA = sA + (kc % 3) * 4096;
        const float* cB = sB + (kc % 3) * 4096;
        #pragma unroll
        for (int ks = 0; ks < 4; ks++) {
            uint32_t bf[4][2];
            #pragma unroll
            for (int nt2 = 0; nt2 < 4; nt2++) {
                int nt = wn * 4 + nt2;
                float2 b2 = *(const float2*)&cB[(nt * 4 + ks) * 64 + lid * 2];
                bf[nt2][0] = F2U(b2.x);
                bf[nt2][1] = F2U(b2.y);
            }
            #pragma unroll
            for (int mt2 = 0; mt2 < 4; mt2++) {
                int mt = wm * 4 + mt2;
                float4 a4 = *(const float4*)&cA[(mt * 4 + ks) * 128 + lid * 4];
                #pragma unroll
                for (int nt2 = 0; nt2 < 4; nt2++)
                    mma_tf32(acc[mt2][nt2][0], acc[mt2][nt2][1],
                             acc[mt2][nt2][2], acc[mt2][nt2][3],
                             F2U(a4.x), F2U(a4.y), F2U(a4.z), F2U(a4.w),
                             bf[nt2][0], bf[nt2][1]);
            }
        }
        __syncthreads();
    }

    // epilogue -> g_attout A-frag-permuted 64-row tiles
    int rg = lid >> 2, q2 = (lid & 3) * 2;
    #pragma unroll
    for (int mt2 = 0; mt2 < 4; mt2++) {
        int rowA = i0 + wm * 64 + mt2 * 16 + rg;
        int rt = rowA & 63;
        #pragma unroll
        for (int nt2 = 0; nt2 < 4; nt2++) {
            int col = n0 + wn * 32 + nt2 * 8 + q2;
            int n = col >> 4, d = col & 15;
            int c = h * DV + d;
            size_t r = (size_t)n * L + rowA;
            float* p = g_attout + (r >> 6) * 4096;
            int base = afrag_addr(rt, c, 8);
            p[base]     = acc[mt2][nt2][0];
            p[base + 4] = acc[mt2][nt2][1];
            p[base + 1] = acc[mt2][nt2][2];
            p[base + 5] = acc[mt2][nt2][3];
        }
    }
}

// =====================================================================
// K5 (mma tf32): msax = msa + attout@Wo + bo.  A pre-permuted in gmem.
// =====================================================================
__global__ void __launch_bounds__(256) oproj_mma_kernel(
        const float* __restrict__ msa,
        const float* __restrict__ Wo, const float* __restrict__ bo) {
    __shared__ float Wop[4096];
    __shared__ float Ap[4096];
    __shared__ float sbo[DM];
    int t = threadIdx.x, warp = t >> 5, lane = t & 31;
    int rg = lane >> 2, q2 = (lane & 3) * 2;

    for (int i = t; i < 4096; i += 256) {
        int c = i >> 6, n = i & 63;
        Wop[bfrag_addr(c, n, 8)] = Wo[i];
    }
    if (t < DM) sbo[t] = bo[t];
    __syncthreads();

    int wm = warp >> 2, wn = warp & 3;
    for (int tile = blockIdx.x; tile < NROWS / 64; tile += gridDim.x) {
        size_t row0 = (size_t)tile * 64;
        const float4* src = (const float4*)(g_attout + (size_t)tile * 4096);
        #pragma unroll
        for (int u = 0; u < 4; u++) {
            int id = t + u * 256;
            *(float4*)&Ap[id * 4] = src[id];
        }
        __syncthreads();
        float acc[2][2][4];
        #pragma unroll
        for (int x = 0; x < 2; x++)
            #pragma unroll
            for (int y = 0; y < 2; y++)
                #pragma unroll
                for (int r = 0; r < 4; r++) acc[x][y][r] = 0.0f;
        #pragma unroll
        for (int ks = 0; ks < 8; ks++) {
            float4 af[2];
            float2 bf[2];
            #pragma unroll
            for (int mt = 0; mt < 2; mt++)
                af[mt] = *(const float4*)&Ap[((wm * 2 + mt) * 8 + ks) * 128 + lane * 4];
            #pragma unroll
            for (int nt = 0; nt < 2; nt++)
                bf[nt] = *(const float2*)&Wop[((wn * 2 + nt) * 8 + ks) * 64 + lane * 2];
            #pragma unroll
            for (int mt = 0; mt < 2; mt++)
                #pragma unroll
                for (int nt = 0; nt < 2; nt++)
                    mma_tf32(acc[mt][nt][0], acc[mt][nt][1], acc[mt][nt][2], acc[mt][nt][3],
                             F2U(af[mt].x), F2U(af[mt].y), F2U(af[mt].z), F2U(af[mt].w),
                             F2U(bf[nt].x), F2U(bf[nt].y));
        }
        #pragma unroll
        for (int mt = 0; mt < 2; mt++) {
            #pragma unroll
            for (int nt = 0; nt < 2; nt++) {
                int rt0 = wm * 32 + mt * 16 + rg;
                int c0 = wn * 16 + nt * 8 + q2;
                float bo0 = sbo[c0], bo1 = sbo[c0 + 1];
                #pragma unroll
                for (int half = 0; half < 2; half++) {
                    size_t r = row0 + rt0 + half * 8;
                    float2 m2 = *(const float2*)&msa[r * DM + c0];
                    float2 y = make_float2(acc[mt][nt][half * 2]     + bo0 + m2.x,
                                           acc[mt][nt][half * 2 + 1] + bo1 + m2.y);
                    *(float2*)&g_msax[r * DM + c0] = y;
                }
            }
        }
        __syncthreads();
    }
}

// =====================================================================
// K6 (mma tf32): fused FF + final LN (validated R5/R6).
// =====================================================================
struct FFS3 {
    float W1p[DM * FFH];
    float W2p[FFH * DM];
    float b1s[FFH];
    float b2s[DM], g2[DM], bn2[DM], g3[DM], bn3[DM];
    float Xs[64 * DM];
    float Ap[64 * DM];
    float Hp[64 * FFH];
};
extern __shared__ unsigned char ff_raw[];

__global__ void __launch_bounds__(256) ff_mma_kernel(
        const float* __restrict__ n2g, const float* __restrict__ n2b,
        const float* __restrict__ W1, const float* __restrict__ b1,
        const float* __restrict__ W2, const float* __restrict__ b2,
        const float* __restrict__ n3g, const float* __restrict__ n3b,
        float* __restrict__ out) {
    FFS3* s = (FFS3*)ff_raw;
    int t = threadIdx.x, warp = t >> 5, lane = t & 31;
    int rg = lane >> 2, q2 = (lane & 3) * 2;

    for (int i = t; i < DM * FFH; i += 256) {
        int c = i >> 8, n = i & 255;
        s->W1p[bfrag_addr(c, n, 8)] = W1[i];
    }
    for (int i = t; i < FFH * DM; i += 256) {
        int c = i >> 6, n = i & 63;
        s->W2p[bfrag_addr(c, n, 32)] = W2[i];
    }
    s->b1s[t] = b1[t];
    if (t < DM) { s->b2s[t] = b2[t]; s->g2[t] = n2g[t]; s->bn2[t] = n2b[t];
                  s->g3[t] = n3g[t]; s->bn3[t] = n3b[t]; }
    __syncthreads();

    const int nTiles = NROWS / 64;
    for (int tile = blockIdx.x; tile < nTiles; tile += gridDim.x) {
        size_t row0 = (size_t)tile * 64;
        #pragma unroll
        for (int i = 0; i < 4; i++) {
            int f4 = t * 4 + i;
            *(float4*)&s->Xs[f4 * 4] = *(const float4*)&g_msax[row0 * DM + f4 * 4];
        }
        __syncthreads();
        #pragma unroll
        for (int rr = 0; rr < 8; rr++) {
            int row = warp * 8 + rr;
            float2 x2 = *(const float2*)&s->Xs[row * DM + 2 * lane];
            float sum = x2.x + x2.y;
            #pragma unroll
            for (int o = 16; o; o >>= 1) sum += __shfl_xor_sync(0xffffffffu, sum, o);
            float m = sum * (1.0f / DM);
            float d0 = x2.x - m, d1 = x2.y - m;
            float vv = d0 * d0 + d1 * d1;
            #pragma unroll
            for (int o = 16; o; o >>= 1) vv += __shfl_xor_sync(0xffffffffu, vv, o);
            float r = rsqrtf(vv * (1.0f / DM) + EPSLN);
            int c0 = 2 * lane;
            s->Ap[afrag_addr(row, c0, 8)]     = d0 * r * s->g2[c0]     + s->bn2[c0];
            s->Ap[afrag_addr(row, c0 + 1, 8)] = d1 * r * s->g2[c0 + 1] + s->bn2[c0 + 1];
        }
        __syncthreads();
        {
            int wm = warp >> 2, wn = warp & 3;
            float acc1[2][8][4];
            #pragma unroll
            for (int x = 0; x < 2; x++)
                #pragma unroll
                for (int y = 0; y < 8; y++)
                    #pragma unroll
                    for (int r = 0; r < 4; r++) acc1[x][y][r] = 0.0f;
            #pragma unroll
            for (int ks = 0; ks < 8; ks++) {
                float4 af0 = *(const float4*)&s->Ap[((wm * 2 + 0) * 8 + ks) * 128 + lane * 4];
                float4 af1 = *(const float4*)&s->Ap[((wm * 2 + 1) * 8 + ks) * 128 + lane * 4];
                #pragma unroll
                for (int nt = 0; nt < 8; nt++) {
                    float2 b2v = *(const float2*)&s->W1p[((wn * 8 + nt) * 8 + ks) * 64 + lane * 2];
                    mma_tf32(acc1[0][nt][0], acc1[0][nt][1], acc1[0][nt][2], acc1[0][nt][3],
                             F2U(af0.x), F2U(af0.y), F2U(af0.z), F2U(af0.w),
                             F2U(b2v.x), F2U(b2v.y));
                    mma_tf32(acc1[1][nt][0], acc1[1][nt][1], acc1[1][nt][2], acc1[1][nt][3],
                             F2U(af1.x), F2U(af1.y), F2U(af1.z), F2U(af1.w),
                             F2U(b2v.x), F2U(b2v.y));
                }
            }
            #pragma unroll
            for (int mt = 0; mt < 2; mt++) {
                int mt2 = wm * 2 + mt;
                #pragma unroll
                for (int nt = 0; nt < 8; nt++) {
                    int ks2 = wn * 8 + nt;
                    int c0 = ks2 * 8 + q2;
                    float b1a = s->b1s[c0], b1b = s->b1s[c0 + 1];
                    float v0 = fmaxf(acc1[mt][nt][0] + b1a, 0.f);
                    float v1 = fmaxf(acc1[mt][nt][1] + b1b, 0.f);
                    float v2 = fmaxf(acc1[mt][nt][2] + b1a, 0.f);
                    float v3 = fmaxf(acc1[mt][nt][3] + b1b, 0.f);
                    int fb = (mt2 * 32 + ks2) * 128 + rg * 16;
                    int a0 = fb + (q2 & 3) * 4 + ((q2 >> 2) << 1);
                    int kk1 = q2 + 1;
                    int a1 = fb + (kk1 & 3) * 4 + ((kk1 >> 2) << 1);
                    *(float2*)&s->Hp[a0] = make_float2(v0, v2);
                    *(float2*)&s->Hp[a1] = make_float2(v1, v3);
                }
            }
        }
        __syncthreads();
        {
            int kg = warp >> 2, wm2 = (warp >> 1) & 1, wn2 = warp & 1;
            float acc2[2][4][4];
            #pragma unroll
            for (int x = 0; x < 2; x++)
                #pragma unroll
                for (int y = 0; y < 4; y++)
                    #pragma unroll
                    for (int r = 0; r < 4; r++) acc2[x][y][r] = 0.0f;
            #pragma unroll 8
            for (int ks = 0; ks < 16; ks++) {
                int ksg = kg * 16 + ks;
                float4 af0 = *(const float4*)&s->Hp[((wm2 * 2 + 0) * 32 + ksg) * 128 + lane * 4];
                float4 af1 = *(const float4*)&s->Hp[((wm2 * 2 + 1) * 32 + ksg) * 128 + lane * 4];
                #pragma unroll
                for (int nt = 0; nt < 4; nt++) {
                    float2 b2v = *(const float2*)&s->W2p[((wn2 * 4 + nt) * 32 + ksg) * 64 + lane * 2];
                    mma_tf32(acc2[0][nt][0], acc2[0][nt][1], acc2[0][nt][2], acc2[0][nt][3],
                             F2U(af0.x), F2U(af0.y), F2U(af0.z), F2U(af0.w),
                             F2U(b2v.x), F2U(b2v.y));
                    mma_tf32(acc2[1][nt][0], acc2[1][nt][1], acc2[1][nt][2], acc2[1][nt][3],
                             F2U(af1.x), F2U(af1.y), F2U(af1.z), F2U(af1.w),
                             F2U(b2v.x), F2U(b2v.y));
                }
            }
            __syncthreads();
            float* Ps = s->Hp;
            #pragma unroll
            for (int mt = 0; mt < 2; mt++)
                #pragma unroll
                for (int nt = 0; nt < 4; nt++) {
                    int r0 = wm2 * 32 + mt * 16 + rg;
                    int c0 = wn2 * 32 + nt * 8 + q2;
                    *(float2*)&Ps[kg * 4608 + r0 * 72 + c0] =
                        make_float2(acc2[mt][nt][0], acc2[mt][nt][1]);
                    *(float2*)&Ps[kg * 4608 + (r0 + 8) * 72 + c0] =
                        make_float2(acc2[mt][nt][2], acc2[mt][nt][3]);
                }
        }
        __syncthreads();
        {
            float* Ps = s->Hp;
            #pragma unroll
            for (int rr = 0; rr < 8; rr++) {
                int row = warp * 8 + rr;
                float2 x2 = *(const float2*)&s->Xs[row * DM + 2 * lane];
                float2 p0 = *(const float2*)&Ps[row * 72 + 2 * lane];
                float2 p1 = *(const float2*)&Ps[4608 + row * 72 + 2 * lane];
                float y0 = x2.x + s->b2s[2 * lane]     + p0.x + p1.x;
                float y1 = x2.y + s->b2s[2 * lane + 1] + p0.y + p1.y;
                float sum = y0 + y1;
                #pragma unroll
                for (int o = 16; o; o >>= 1) sum += __shfl_xor_sync(0xffffffffu, sum, o);
                float m = sum * (1.0f / DM);
                float d0 = y0 - m, d1 = y1 - m;
                float vv = d0 * d0 + d1 * d1;
                #pragma unroll
                for (int o = 16; o; o >>= 1) vv += __shfl_xor_sync(0xffffffffu, vv, o);
                float r = rsqrtf(vv * (1.0f / DM) + EPSLN);
                size_t ob = (row0 + row) * DM;
                out[ob + 2 * lane]     = d0 * r * s->g3[2 * lane]     + s->bn3[2 * lane];
                out[ob + 2 * lane + 1] = d1 * r * s->g3[2 * lane + 1] + s->bn3[2 * lane + 1];
            }
        }
        __syncthreads();
    }
}

// =====================================================================
extern "C" void kernel_launch(void* const* d_in, const int* in_sizes, int n_in,
                              void* d_out, int out_size) {
    const float* msa   = (const float*)d_in[0];
    const float* Ca    = (const float*)d_in[1];
    const float* state = (const float*)d_in[2];
    const float* ns_g  = (const float*)d_in[3];
    const float* ns_b  = (const float*)d_in[4];
    const float* n1_g  = (const float*)d_in[5];
    const float* n1_b  = (const float*)d_in[6];
    const float* Wq    = (const float*)d_in[7];
    const float* bq    = (const float*)d_in[8];
    const float* Wk    = (const float*)d_in[9];
    const float* bk    = (const float*)d_in[10];
    const float* Wv    = (const float*)d_in[11];
    const float* bv    = (const float*)d_in[12];
    const float* Wo    = (const float*)d_in[13];
    const float* bo    = (const float*)d_in[14];
    const float* n2_g  = (const float*)d_in[15];
    const float* n2_b  = (const float*)d_in[16];
    const float* W1    = (const float*)d_in[17];
    const float* b1    = (const float*)d_in[18];
    const float* W2    = (const float*)d_in[19];
    const float* b2    = (const float*)d_in[20];
    const float* n3_g  = (const float*)d_in[21];
    const float* n3_b  = (const float*)d_in[22];
    float* out = (float*)d_out;

    cudaFuncSetAttribute(ff_mma_kernel, cudaFuncAttributeMaxDynamicSharedMemorySize,
                         (int)sizeof(FFS3));
    cudaFuncSetAttribute(gemm_attn_mma, cudaFuncAttributeMaxDynamicSharedMemorySize,
                         98304);

    qk_kernel<<<L, 128>>>(state, ns_g, ns_b, Wq, bq, Wk, bk);
    attn_kernel<<<dim3(L, NH), 256>>>(Ca);
    v_mma_kernel<<<1024, 256>>>(msa, n1_g, n1_b, Wv, bv);
    gemm_attn_mma<<<dim3(32, 4, 4), 256, 98304>>>();
    oproj_mma_kernel<<<1024, 256>>>(msa, Wo, bo);
    ff_mma_kernel<<<148, 256, sizeof(FFS3)>>>(n2_g, n2_b, W1, b1, W2, b2, n3_g, n3_b, out);
}

// round 9
// speedup vs baseline: 4.3757x; 1.0449x over previous
#include <cuda_runtime.h>
#include <cuda_bf16.h>
#include <math.h>
#include <stdint.h>

// ---------------- problem constants ----------------
#define L 512
#define NSEQ 256
#define DM 64
#define DS 32
#define NH 4
#define DK 32
#define DV 16
#define FFH 256
#define NROWS (NSEQ * L)
#define EPSLN 1e-5f
#define NEGMAX (-3.402823466e38f)

// ---------------- scratch ----------------
__device__ float g_q[L * NH * DK];
__device__ float g_k[L * NH * DK];
__device__ float g_attn[NH * L * L];          // A-frag: [h][iblk(4)][kc(16)][4096]
__device__ float g_vT[NH * L * NSEQ * DV];    // B-frag: [h][nblk(32)][kc(16)][4096]
__device__ float g_attout[NROWS * DM];        // A-frag 64-row tiles: [tile][4096]
__device__ float g_msax[NROWS * DM];          // raw rows

__device__ __forceinline__ void mma_tf32(float& c0, float& c1, float& c2, float& c3,
                                         uint32_t a0, uint32_t a1, uint32_t a2, uint32_t a3,
                                         uint32_t b0, uint32_t b1) {
    asm volatile(
        "mma.sync.aligned.m16n8k8.row.col.f32.tf32.tf32.f32 "
        "{%0,%1,%2,%3}, {%4,%5,%6,%7}, {%8,%9}, {%0,%1,%2,%3};"
        : "+f"(c0), "+f"(c1), "+f"(c2), "+f"(c3)
        : "r"(a0), "r"(a1), "r"(a2), "r"(a3), "r"(b0), "r"(b1));
}
#define F2U(x) __float_as_uint(x)

__device__ __forceinline__ uint32_t smem_u32(const void* p) {
    uint32_t a;
    asm("{ .reg .u64 tmp; cvta.to.shared.u64 tmp, %1; cvt.u32.u64 %0, tmp; }"
        : "=r"(a) : "l"(p));
    return a;
}
__device__ __forceinline__ void cp16(uint32_t smem, const void* gmem) {
    asm volatile("cp.async.cg.shared.global [%0], [%1], 16;" :: "r"(smem), "l"(gmem));
}
#define CP_COMMIT() asm volatile("cp.async.commit_group;")
#define CP_WAIT2()  asm volatile("cp.async.wait_group 2;")

__device__ __forceinline__ int afrag_addr(int r, int c, int KS8) {
    return ((r >> 4) * KS8 + (c >> 3)) * 128 + (r & 7) * 16 + ((r >> 3) & 1)
         + (c & 3) * 4 + ((c >> 2) & 1) * 2;
}
__device__ __forceinline__ int bfrag_addr(int c, int n, int KS8) {
    return ((n >> 3) * KS8 + (c >> 3)) * 64 + (n & 7) * 8 + (c & 3) * 2 + ((c >> 2) & 1);
}

// =====================================================================
// K1: st = LN(state); q,k projections.  grid=512, block=128
// =====================================================================
__global__ void qk_kernel(const float* __restrict__ state,
                          const float* __restrict__ nsg, const float* __restrict__ nsb,
                          const float* __restrict__ Wq, const float* __restrict__ bq,
                          const float* __restrict__ Wk, const float* __restrict__ bk) {
    int l = blockIdx.x;
    int t = threadIdx.x;
    __shared__ float st[DS];
    if (t < DS) {
        float x = state[l * DS + t];
        float s = x;
        #pragma unroll
        for (int o = 16; o; o >>= 1) s += __shfl_xor_sync(0xffffffffu, s, o);
        float m = s * (1.0f / DS);
        float d = x - m;
        float v = d * d;
        #pragma unroll
        for (int o = 16; o; o >>= 1) v += __shfl_xor_sync(0xffffffffu, v, o);
        float r = rsqrtf(v * (1.0f / DS) + EPSLN);
        st[t] = d * r * nsg[t] + nsb[t];
    }
    __syncthreads();
    float aq = bq[t], ak = bk[t];
    #pragma unroll
    for (int c = 0; c < DS; c++) {
        float s = st[c];
        aq += s * Wq[c * 128 + t];
        ak += s * Wk[c * 128 + t];
    }
    g_q[l * 128 + t] = aq;
    g_k[l * 128 + t] = ak;
}

// =====================================================================
// K2 (fused): blocks [0,1024) = v path (LN1 + Wv mma -> g_vT B-frags,
// staged + coalesced); blocks [1024,3072) = attn softmax -> g_attn A-frags.
// =====================================================================
__global__ void __launch_bounds__(256) prep_kernel(
        const float* __restrict__ Ca,
        const float* __restrict__ msa,
        const float* __restrict__ n1g, const float* __restrict__ n1b,
        const float* __restrict__ Wv, const float* __restrict__ bv) {
    __shared__ float Wvp[4096];
    __shared__ float Ap[4096];
    __shared__ float sbv[DM], sg[DM], sb[DM];
    __shared__ float qv[DK];
    __shared__ float red[8];
    __shared__ float cai[3];

    int t = threadIdx.x;

    if (blockIdx.x < 1024) {
        // ================= v path =================
        int warp = t >> 5, lane = t & 31;
        int rg = lane >> 2, q2 = (lane & 3) * 2;
        for (int i = t; i < 4096; i += 256) {
            int c = i >> 6, n = i & 63;
            Wvp[bfrag_addr(c, n, 8)] = Wv[i];
        }
        if (t < DM) { sbv[t] = bv[t]; sg[t] = n1g[t]; sb[t] = n1b[t]; }
        __syncthreads();

        int wm = warp >> 2, wn = warp & 3;
        for (int tile = blockIdx.x; tile < NROWS / 64; tile += 1024) {
            size_t row0 = (size_t)tile * 64;
            #pragma unroll
            for (int rr = 0; rr < 8; rr++) {
                int row = warp * 8 + rr;
                float2 x2 = *(const float2*)&msa[(row0 + row) * DM + 2 * lane];
                float sum = x2.x + x2.y;
                #pragma unroll
                for (int o = 16; o; o >>= 1) sum += __shfl_xor_sync(0xffffffffu, sum, o);
                float m = sum * (1.0f / DM);
                float d0 = x2.x - m, d1 = x2.y - m;
                float vv = d0 * d0 + d1 * d1;
                #pragma unroll
                for (int o = 16; o; o >>= 1) vv += __shfl_xor_sync(0xffffffffu, vv, o);
                float r = rsqrtf(vv * (1.0f / DM) + EPSLN);
                int c0 = 2 * lane;
                Ap[afrag_addr(row, c0, 8)]     = d0 * r * sg[c0]     + sb[c0];
                Ap[afrag_addr(row, c0 + 1, 8)] = d1 * r * sg[c0 + 1] + sb[c0 + 1];
            }
            __syncthreads();
            float acc[2][2][4];
            #pragma unroll
            for (int x = 0; x < 2; x++)
                #pragma unroll
                for (int y = 0; y < 2; y++)
                    #pragma unroll
                    for (int r = 0; r < 4; r++) acc[x][y][r] = 0.0f;
            #pragma unroll
            for (int ks = 0; ks < 8; ks++) {
                float4 af[2];
                float2 bf[2];
                #pragma unroll
                for (int mt = 0; mt < 2; mt++)
                    af[mt] = *(const float4*)&Ap[((wm * 2 + mt) * 8 + ks) * 128 + lane * 4];
                #pragma unroll
                for (int nt = 0; nt < 2; nt++)
                    bf[nt] = *(const float2*)&Wvp[((wn * 2 + nt) * 8 + ks) * 64 + lane * 2];
                #pragma unroll
                for (int mt = 0; mt < 2; mt++)
                    #pragma unroll
                    for (int nt = 0; nt < 2; nt++)
                        mma_tf32(acc[mt][nt][0], acc[mt][nt][1], acc[mt][nt][2], acc[mt][nt][3],
                                 F2U(af[mt].x), F2U(af[mt].y), F2U(af[mt].z), F2U(af[mt].w),
                                 F2U(bf[nt].x), F2U(bf[nt].y));
            }
            __syncthreads();          // all Ap reads done -> reuse as staging
            // stage C-frags (+bv) into Ap in bfrag-block layout
            #pragma unroll
            for (int mt = 0; mt < 2; mt++) {
                #pragma unroll
                for (int nt = 0; nt < 2; nt++) {
                    int rt0 = wm * 32 + mt * 16 + rg;
                    int c0 = wn * 16 + nt * 8 + q2;
                    #pragma unroll
                    for (int e = 0; e < 4; e++) {
                        int rt = rt0 + (e >> 1) * 8;
                        int cc = c0 + (e & 1);
                        int h = cc >> 4, d = cc & 15;
                        int sidx = ((((h * 2 + (rt >> 5)) * 2 + (d >> 3)) * 4)
                                    + ((rt >> 3) & 3)) * 64
                                 + (d & 7) * 8 + (rt & 3) * 2 + ((rt >> 2) & 1);
                        Ap[sidx] = acc[mt][nt][e] + sbv[cc];
                    }
                }
            }
            __syncthreads();
            // coalesced copyout: 64 blocks x 64 floats
            {
                int n = (int)(row0 >> 9);
                int j0s = (int)((row0 & 511) >> 5);
                int blk = n >> 3;
                #pragma unroll
                for (int u = 0; u < 4; u++) {
                    int f = t + u * 256;
                    int b = f >> 4;
                    int off = (f & 15) * 4;
                    int h = b >> 4, kcl = (b >> 3) & 1, dhi = (b >> 2) & 1, krhi = b & 3;
                    size_t dst = ((size_t)(h * 32 + blk) * 16 + j0s + kcl) * 4096
                               + (size_t)((((n & 7) * 2 + dhi) * 4 + krhi) * 64 + off);
                    *(float4*)&g_vT[dst] = *(const float4*)&Ap[b * 64 + off];
                }
            }
            __syncthreads();
        }
    } else {
        // ================= attn path =================
        int idx = blockIdx.x - 1024;
        int i = idx & 511, h = idx >> 9;
        if (t < DK) qv[t] = g_q[i * 128 + h * DK + t];
        if (t < 3)  cai[t] = Ca[i * 3 + t];
        __syncthreads();

        float bin = (float)(4 * (h + 1)) / 10.0f;
        float bin2 = bin * bin;
        const float scaling = 0.17677669529663687f;
        float cx = cai[0], cy = cai[1], cz = cai[2];

        float sc[2];
        #pragma unroll
        for (int u = 0; u < 2; u++) {
            int j = t + u * 256;
            float dx = Ca[3 * j] - cx, dy = Ca[3 * j + 1] - cy, dz = Ca[3 * j + 2] - cz;
            float sq = fmaxf(dx * dx + dy * dy + dz * dz, 1e-12f);
            if (sq > bin2) {
                sc[u] = NEGMAX;
            } else {
                float a = 0.0f;
                const float* kp = &g_k[j * 128 + h * DK];
                #pragma unroll
                for (int d = 0; d < DK; d++) a += qv[d] * kp[d];
                sc[u] = a * scaling;
            }
        }
        float mx = fmaxf(sc[0], sc[1]);
        #pragma unroll
        for (int o = 16; o; o >>= 1) mx = fmaxf(mx, __shfl_xor_sync(0xffffffffu, mx, o));
        if ((t & 31) == 0) red[t >> 5] = mx;
        __syncthreads();
        mx = red[0];
        #pragma unroll
        for (int w = 1; w < 8; w++) mx = fmaxf(mx, red[w]);

        float e0 = expf(sc[0] - mx);
        float e1 = expf(sc[1] - mx);
        float ss = e0 + e1;
        #pragma unroll
        for (int o = 16; o; o >>= 1) ss += __shfl_xor_sync(0xffffffffu, ss, o);
        __syncthreads();
        if ((t & 31) == 0) red[t >> 5] = ss;
        __syncthreads();
        ss = red[0];
        #pragma unroll
        for (int w = 1; w < 8; w++) ss += red[w];
        float inv = 1.0f / ss;

        int iblk = i >> 7, ib = i & 127;
        size_t blkbase = ((size_t)(h * 4 + iblk) * 16) * 4096;
        float vals[2] = {e0 * inv, e1 * inv};
        #pragma unroll
        for (int u = 0; u < 2; u++) {
            int j = t + u * 256;
            int kc = j >> 5;
            g_attn[blkbase + (size_t)kc * 4096 + afrag_addr(ib, j & 31, 4)] = vals[u];
        }
    }
}

// =====================================================================
// K4 (mma tf32 + cp.async 3-stage): per-head C = attn @ vT.
// Epilogue staged through smem -> coalesced STG.128.  grid=(32,4,4).
// =====================================================================
extern __shared__ float gsh[];
__global__ void __launch_bounds__(256, 2) gemm_attn_mma() {
    int h  = blockIdx.z;
    const float* __restrict__ Abase =
        g_attn + ((size_t)(h * 4 + blockIdx.y) * 16) * 4096;
    const float* __restrict__ Bbase =
        g_vT + ((size_t)(h * 32 + blockIdx.x) * 16) * 4096;

    float* sA = gsh;
    float* sB = gsh + 12288;

    int t = threadIdx.x, wid = t >> 5, lid = t & 31;
    int wm = wid >> 2, wn = wid & 3;
    uint32_t aAddr = smem_u32(sA) + t * 16;
    uint32_t bAddr = smem_u32(sB) + t * 16;

    float acc[4][4][4];
    #pragma unroll
    for (int x = 0; x < 4; x++)
        #pragma unroll
        for (int y = 0; y < 4; y++)
            #pragma unroll
            for (int r = 0; r < 4; r++) acc[x][y][r] = 0.0f;

    #pragma unroll 1
    for (int p = 0; p < 2; p++) {
        const float4* srcA = (const float4*)(Abase + (size_t)p * 4096) + t;
        const float4* srcB = (const float4*)(Bbase + (size_t)p * 4096) + t;
        #pragma unroll
        for (int u = 0; u < 4; u++) {
            cp16(aAddr + p * 16384 + u * 4096, srcA + u * 256);
            cp16(bAddr + p * 16384 + u * 4096, srcB + u * 256);
        }
        CP_COMMIT();
    }

    #pragma unroll 1
    for (int kc = 0; kc < 16; kc++) {
        if (kc + 2 < 16) {
            int st = (kc + 2) % 3;
            const float4* srcA = (const float4*)(Abase + (size_t)(kc + 2) * 4096) + t;
            const float4* srcB = (const float4*)(Bbase + (size_t)(kc + 2) * 4096) + t;
            #pragma unroll
            for (int u = 0; u < 4; u++) {
                cp16(aAddr + st * 16384 + u * 4096, srcA + u * 256);
                cp16(bAddr + st * 16384 + u * 4096, srcB + u * 256);
            }
        }
        CP_COMMIT();
        CP_WAIT2();
        __syncthreads();
        const float* cA = sA + (kc % 3) * 4096;
        const float* cB = sB + (kc % 3) * 4096;
        #pragma unroll
        for (int ks = 0; ks < 4; ks++) {
            uint32_t bf[4][2];
            #pragma unroll
            for (int nt2 = 0; nt2 < 4; nt2++) {
                int nt = wn * 4 + nt2;
                float2 b2 = *(const float2*)&cB[(nt * 4 + ks) * 64 + lid * 2];
                bf[nt2][0] = F2U(b2.x);
                bf[nt2][1] = F2U(b2.y);
            }
            #pragma unroll
            for (int mt2 = 0; mt2 < 4; mt2++) {
                int mt = wm * 4 + mt2;
                float4 a4 = *(const float4*)&cA[(mt * 4 + ks) * 128 + lid * 4];
                #pragma unroll
                for (int nt2 = 0; nt2 < 4; nt2++)
                    mma_tf32(acc[mt2][nt2][0], acc[mt2][nt2][1],
                             acc[mt2][nt2][2], acc[mt2][nt2][3],
                             F2U(a4.x), F2U(a4.y), F2U(a4.z), F2U(a4.w),
                             bf[nt2][0], bf[nt2][1]);
            }
        }
        __syncthreads();
    }

    // ---- staged epilogue: C-frags -> smem (afrag-block layout) -> coalesced STG ----
    float* stg = gsh;                 // 16384 floats, pipeline buffers dead
    int rg = lid >> 2, q2 = (lid & 3) * 2;
    #pragma unroll
    for (int mt2 = 0; mt2 < 4; mt2++) {
        #pragma unroll
        for (int nt2 = 0; nt2 < 4; nt2++) {
            int nloc = wn * 2 + (nt2 >> 1);
            #pragma unroll
            for (int e = 0; e < 4; e++) {
                int rt = mt2 * 16 + rg + (e >> 1) * 8;
                int d = (nt2 & 1) * 8 + q2 + (e & 1);
                int sidx = (((wm * 8 + nloc) * 2 + (d >> 3)) * 4 + mt2) * 128
                         + (rt & 7) * 16 + ((rt >> 3) & 1)
                         + (d & 3) * 4 + ((d >> 2) & 1) * 2;
                stg[sidx] = acc[mt2][nt2][e];
            }
        }
    }
    __syncthreads();
    #pragma unroll
    for (int u = 0; u < 16; u++) {
        int f = t + u * 256;          // 0..4095 float4s
        int b = f >> 5;               // 0..127
        int off = (f & 31) * 4;
        int krt = b & 3, dhi = (b >> 2) & 1, nloc = (b >> 3) & 7, iloc = b >> 6;
        int n = blockIdx.x * 8 + nloc;
        size_t rtile = (size_t)n * 8 + blockIdx.y * 2 + iloc;
        size_t dst = rtile * 4096 + (size_t)((krt * 8 + h * 2 + dhi) * 128 + off);
        *(float4*)&g_attout[dst] = *(const float4*)&stg[b * 128 + off];
    }
}

// =====================================================================
// K5 (mma tf32): msax = msa + attout@Wo + bo.
// =====================================================================
__global__ void __launch_bounds__(256) oproj_mma_kernel(
        const float* __restrict__ msa,
        const float* __restrict__ Wo, const float* __restrict__ bo) {
    __shared__ float Wop[4096];
    __shared__ float Ap[4096];
    __shared__ float sbo[DM];
    int t = threadIdx.x, warp = t >> 5, lane = t & 31;
    int rg = lane >> 2, q2 = (lane & 3) * 2;

    for (int i = t; i < 4096; i += 256) {
        int c = i >> 6, n = i & 63;
        Wop[bfrag_addr(c, n, 8)] = Wo[i];
    }
    if (t < DM) sbo[t] = bo[t];
    __syncthreads();

    int wm = warp >> 2, wn = warp & 3;
    for (int tile = blockIdx.x; tile < NROWS / 64; tile += gridDim.x) {
        size_t row0 = (size_t)tile * 64;
        const float4* src = (const float4*)(g_attout + (size_t)tile * 4096);
        #pragma unroll
        for (int u = 0; u < 4; u++) {
            int id = t + u * 256;
            *(float4*)&Ap[id * 4] = src[id];
        }
        __syncthreads();
        float acc[2][2][4];
        #pragma unroll
        for (int x = 0; x < 2; x++)
            #pragma unroll
            for (int y = 0; y < 2; y++)
                #pragma unroll
                for (int r = 0; r < 4; r++) acc[x][y][r] = 0.0f;
        #pragma unroll
        for (int ks = 0; ks < 8; ks++) {
            float4 af[2];
            float2 bf[2];
            #pragma unroll
            for (int mt = 0; mt < 2; mt++)
                af[mt] = *(const float4*)&Ap[((wm * 2 + mt) * 8 + ks) * 128 + lane * 4];
            #pragma unroll
            for (int nt = 0; nt < 2; nt++)
                bf[nt] = *(const float2*)&Wop[((wn * 2 + nt) * 8 + ks) * 64 + lane * 2];
            #pragma unroll
            for (int mt = 0; mt < 2; mt++)
                #pragma unroll
                for (int nt = 0; nt < 2; nt++)
                    mma_tf32(acc[mt][nt][0], acc[mt][nt][1], acc[mt][nt][2], acc[mt][nt][3],
                             F2U(af[mt].x), F2U(af[mt].y), F2U(af[mt].z), F2U(af[mt].w),
                             F2U(bf[nt].x), F2U(bf[nt].y));
        }
        #pragma unroll
        for (int mt = 0; mt < 2; mt++) {
            #pragma unroll
            for (int nt = 0; nt < 2; nt++) {
                int rt0 = wm * 32 + mt * 16 + rg;
                int c0 = wn * 16 + nt * 8 + q2;
                float bo0 = sbo[c0], bo1 = sbo[c0 + 1];
                #pragma unroll
                for (int half = 0; half < 2; half++) {
                    size_t r = row0 + rt0 + half * 8;
                    float2 m2 = *(const float2*)&msa[r * DM + c0];
                    float2 y = make_float2(acc[mt][nt][half * 2]     + bo0 + m2.x,
                                           acc[mt][nt][half * 2 + 1] + bo1 + m2.y);
                    *(float2*)&g_msax[r * DM + c0] = y;
                }
            }
        }
        __syncthreads();
    }
}

// =====================================================================
// K6 (mma tf32): fused FF + final LN, with register X prefetch.
// =====================================================================
struct FFS3 {
    float W1p[DM * FFH];
    float W2p[FFH * DM];
    float b1s[FFH];
    float b2s[DM], g2[DM], bn2[DM], g3[DM], bn3[DM];
    float Xs[64 * DM];
    float Ap[64 * DM];
    float Hp[64 * FFH];
};
extern __shared__ unsigned char ff_raw[];

__global__ void __launch_bounds__(256) ff_mma_kernel(
        const float* __restrict__ n2g, const float* __restrict__ n2b,
        const float* __restrict__ W1, const float* __restrict__ b1,
        const float* __restrict__ W2, const float* __restrict__ b2,
        const float* __restrict__ n3g, const float* __restrict__ n3b,
        float* __restrict__ out) {
    FFS3* s = (FFS3*)ff_raw;
    int t = threadIdx.x, warp = t >> 5, lane = t & 31;
    int rg = lane >> 2, q2 = (lane & 3) * 2;

    for (int i = t; i < DM * FFH; i += 256) {
        int c = i >> 8, n = i & 255;
        s->W1p[bfrag_addr(c, n, 8)] = W1[i];
    }
    for (int i = t; i < FFH * DM; i += 256) {
        int c = i >> 6, n = i & 63;
        s->W2p[bfrag_addr(c, n, 32)] = W2[i];
    }
    s->b1s[t] = b1[t];
    if (t < DM) { s->b2s[t] = b2[t]; s->g2[t] = n2g[t]; s->bn2[t] = n2b[t];
                  s->g3[t] = n3g[t]; s->bn3[t] = n3b[t]; }
    __syncthreads();

    const int nTiles = NROWS / 64;
    // preload first X tile into registers
    float4 xr[4];
    if (blockIdx.x < nTiles) {
        const float4* src = (const float4*)&g_msax[(size_t)blockIdx.x * 4096];
        #pragma unroll
        for (int i = 0; i < 4; i++) xr[i] = src[t * 4 + i];
    }

    for (int tile = blockIdx.x; tile < nTiles; tile += gridDim.x) {
        size_t row0 = (size_t)tile * 64;
        #pragma unroll
        for (int i = 0; i < 4; i++)
            *(float4*)&s->Xs[(t * 4 + i) * 4] = xr[i];
        __syncthreads();
        // prefetch next tile's X
        int nxt = tile + gridDim.x;
        if (nxt < nTiles) {
            const float4* src = (const float4*)&g_msax[(size_t)nxt * 4096];
            #pragma unroll
            for (int i = 0; i < 4; i++) xr[i] = src[t * 4 + i];
        }
        #pragma unroll
        for (int rr = 0; rr < 8; rr++) {
            int row = warp * 8 + rr;
            float2 x2 = *(const float2*)&s->Xs[row * DM + 2 * lane];
            float sum = x2.x + x2.y;
            #pragma unroll
            for (int o = 16; o; o >>= 1) sum += __shfl_xor_sync(0xffffffffu, sum, o);
            float m = sum * (1.0f / DM);
            float d0 = x2.x - m, d1 = x2.y - m;
            float vv = d0 * d0 + d1 * d1;
            #pragma unroll
            for (int o = 16; o; o >>= 1) vv += __shfl_xor_sync(0xffffffffu, vv, o);
            float r = rsqrtf(vv * (1.0f / DM) + EPSLN);
            int c0 = 2 * lane;
            s->Ap[afrag_addr(row, c0, 8)]     = d0 * r * s->g2[c0]     + s->bn2[c0];
            s->Ap[afrag_addr(row, c0 + 1, 8)] = d1 * r * s->g2[c0 + 1] + s->bn2[c0 + 1];
        }
        __syncthreads();
        {
            int wm = warp >> 2, wn = warp & 3;
            float acc1[2][8][4];
            #pragma unroll
            for (int x = 0; x < 2; x++)
                #pragma unroll
                for (int y = 0; y < 8; y++)
                    #pragma unroll
                    for (int r = 0; r < 4; r++) acc1[x][y][r] = 0.0f;
            #pragma unroll
            for (int ks = 0; ks < 8; ks++) {
                float4 af0 = *(const float4*)&s->Ap[((wm * 2 + 0) * 8 + ks) * 128 + lane * 4];
                float4 af1 = *(const float4*)&s->Ap[((wm * 2 + 1) * 8 + ks) * 128 + lane * 4];
                #pragma unroll
                for (int nt = 0; nt < 8; nt++) {
                    float2 b2v = *(const float2*)&s->W1p[((wn * 8 + nt) * 8 + ks) * 64 + lane * 2];
                    mma_tf32(acc1[0][nt][0], acc1[0][nt][1], acc1[0][nt][2], acc1[0][nt][3],
                             F2U(af0.x), F2U(af0.y), F2U(af0.z), F2U(af0.w),
                             F2U(b2v.x), F2U(b2v.y));
                    mma_tf32(acc1[1][nt][0], acc1[1][nt][1], acc1[1][nt][2], acc1[1][nt][3],
                             F2U(af1.x), F2U(af1.y), F2U(af1.z), F2U(af1.w),
                             F2U(b2v.x), F2U(b2v.y));
                }
            }
            #pragma unroll
            for (int mt = 0; mt < 2; mt++) {
                int mt2 = wm * 2 + mt;
                #pragma unroll
                for (int nt = 0; nt < 8; nt++) {
                    int ks2 = wn * 8 + nt;
                    int c0 = ks2 * 8 + q2;
                    float b1a = s->b1s[c0], b1b = s->b1s[c0 + 1];
                    float v0 = fmaxf(acc1[mt][nt][0] + b1a, 0.f);
                    float v1 = fmaxf(acc1[mt][nt][1] + b1b, 0.f);
                    float v2 = fmaxf(acc1[mt][nt][2] + b1a, 0.f);
                    float v3 = fmaxf(acc1[mt][nt][3] + b1b, 0.f);
                    int fb = (mt2 * 32 + ks2) * 128 + rg * 16;
                    int a0 = fb + (q2 & 3) * 4 + ((q2 >> 2) << 1);
                    int kk1 = q2 + 1;
                    int a1 = fb + (kk1 & 3) * 4 + ((kk1 >> 2) << 1);
                    *(float2*)&s->Hp[a0] = make_float2(v0, v2);
                    *(float2*)&s->Hp[a1] = make_float2(v1, v3);
                }
            }
        }
        __syncthreads();
        {
            int kg = warp >> 2, wm2 = (warp >> 1) & 1, wn2 = warp & 1;
            float acc2[2][4][4];
            #pragma unroll
            for (int x = 0; x < 2; x++)
                #pragma unroll
                for (int y = 0; y < 4; y++)
                    #pragma unroll
                    for (int r = 0; r < 4; r++) acc2[x][y][r] = 0.0f;
            #pragma unroll 8
            for (int ks = 0; ks < 16; ks++) {
                int ksg = kg * 16 + ks;
                float4 af0 = *(const float4*)&s->Hp[((wm2 * 2 + 0) * 32 + ksg) * 128 + lane * 4];
                float4 af1 = *(const float4*)&s->Hp[((wm2 * 2 + 1) * 32 + ksg) * 128 + lane * 4];
                #pragma unroll
                for (int nt = 0; nt < 4; nt++) {
                    float2 b2v = *(const float2*)&s->W2p[((wn2 * 4 + nt) * 32 + ksg) * 64 + lane * 2];
                    mma_tf32(acc2[0][nt][0], acc2[0][nt][1], acc2[0][nt][2], acc2[0][nt][3],
                             F2U(af0.x), F2U(af0.y), F2U(af0.z), F2U(af0.w),
                             F2U(b2v.x), F2U(b2v.y));
                    mma_tf32(acc2[1][nt][0], acc2[1][nt][1], acc2[1][nt][2], acc2[1][nt][3],
                             F2U(af1.x), F2U(af1.y), F2U(af1.z), F2U(af1.w),
                             F2U(b2v.x), F2U(b2v.y));
                }
            }
            __syncthreads();
            float* Ps = s->Hp;
            #pragma unroll
            for (int mt = 0; mt < 2; mt++)
                #pragma unroll
                for (int nt = 0; nt < 4; nt++) {
                    int r0 = wm2 * 32 + mt * 16 + rg;
                    int c0 = wn2 * 32 + nt * 8 + q2;
                    *(float2*)&Ps[kg * 4608 + r0 * 72 + c0] =
                        make_float2(acc2[mt][nt][0], acc2[mt][nt][1]);
                    *(float2*)&Ps[kg * 4608 + (r0 + 8) * 72 + c0] =
                        make_float2(acc2[mt][nt][2], acc2[mt][nt][3]);
                }
        }
        __syncthreads();
        {
            float* Ps = s->Hp;
            #pragma unroll
            for (int rr = 0; rr < 8; rr++) {
                int row = warp * 8 + rr;
                float2 x2 = *(const float2*)&s->Xs[row * DM + 2 * lane];
                float2 p0 = *(const float2*)&Ps[row * 72 + 2 * lane];
                float2 p1 = *(const float2*)&Ps[4608 + row * 72 + 2 * lane];
                float y0 = x2.x + s->b2s[2 * lane]     + p0.x + p1.x;
                float y1 = x2.y + s->b2s[2 * lane + 1] + p0.y + p1.y;
                float sum = y0 + y1;
                #pragma unroll
                for (int o = 16; o; o >>= 1) sum += __shfl_xor_sync(0xffffffffu, sum, o);
                float m = sum * (1.0f / DM);
                float d0 = y0 - m, d1 = y1 - m;
                float vv = d0 * d0 + d1 * d1;
                #pragma unroll
                for (int o = 16; o; o >>= 1) vv += __shfl_xor_sync(0xffffffffu, vv, o);
                float r = rsqrtf(vv * (1.0f / DM) + EPSLN);
                size_t ob = (row0 + row) * DM;
                out[ob + 2 * lane]     = d0 * r * s->g3[2 * lane]     + s->bn3[2 * lane];
                out[ob + 2 * lane + 1] = d1 * r * s->g3[2 * lane + 1] + s->bn3[2 * lane + 1];
            }
        }
        __syncthreads();
    }
}

// =====================================================================
extern "C" void kernel_launch(void* const* d_in, const int* in_sizes, int n_in,
                              void* d_out, int out_size) {
    const float* msa   = (const float*)d_in[0];
    const float* Ca    = (const float*)d_in[1];
    const float* state = (const float*)d_in[2];
    const float* ns_g  = (const float*)d_in[3];
    const float* ns_b  = (const float*)d_in[4];
    const float* n1_g  = (const float*)d_in[5];
    const float* n1_b  = (const float*)d_in[6];
    const float* Wq    = (const float*)d_in[7];
    const float* bq    = (const float*)d_in[8];
    const float* Wk    = (const float*)d_in[9];
    const float* bk    = (const float*)d_in[10];
    const float* Wv    = (const float*)d_in[11];
    const float* bv    = (const float*)d_in[12];
    const float* Wo    = (const float*)d_in[13];
    const float* bo    = (const float*)d_in[14];
    const float* n2_g  = (const float*)d_in[15];
    const float* n2_b  = (const float*)d_in[16];
    const float* W1    = (const float*)d_in[17];
    const float* b1    = (const float*)d_in[18];
    const float* W2    = (const float*)d_in[19];
    const float* b2    = (const float*)d_in[20];
    const float* n3_g  = (const float*)d_in[21];
    const float* n3_b  = (const float*)d_in[22];
    float* out = (float*)d_out;

    cudaFuncSetAttribute(ff_mma_kernel, cudaFuncAttributeMaxDynamicSharedMemorySize,
                         (int)sizeof(FFS3));
    cudaFuncSetAttribute(gemm_attn_mma, cudaFuncAttributeMaxDynamicSharedMemorySize,
                         98304);

    qk_kernel<<<L, 128>>>(state, ns_g, ns_b, Wq, bq, Wk, bk);
    prep_kernel<<<3072, 256>>>(Ca, msa, n1_g, n1_b, Wv, bv);
    gemm_attn_mma<<<dim3(32, 4, 4), 256, 98304>>>();
    oproj_mma_kernel<<<1024, 256>>>(msa, Wo, bo);
    ff_mma_kernel<<<148, 256, sizeof(FFS3)>>>(n2_g, n2_b, W1, b1, W2, b2, n3_g, n3_b, out);
}